// round 4
// baseline (speedup 1.0000x reference)
#include <cuda_runtime.h>
#include <cuda_bf16.h>
#include <cstdint>

// Problem constants (match reference)
#define N_U   100000
#define N_V   100000
#define D_IN  256
#define D_OUT 320
#define S_REL 5
#define E_REL 500000
#define CHUNK 64           // D_OUT / S_REL

// ---------------------------------------------------------------------------
// Scratch: Y_u = x_u @ W, Y_v = x_v @ W  (fp32, 128 MB each, static bss)
// ---------------------------------------------------------------------------
__device__ float g_Yu[(size_t)N_U * D_OUT];
__device__ float g_Yv[(size_t)N_V * D_OUT];

// ---------------------------------------------------------------------------
// SGEMM: C[M, 320] = A[M, 256] @ B[256, 320]
// BM=128, BN=64, BK=16, thread tile 8x4, 256 threads/block
// ---------------------------------------------------------------------------
#define BM 128
#define BN 64
#define BK 16
#define TM 8
#define TN 4

__global__ __launch_bounds__(256)
void sgemm_kernel(const float* __restrict__ A, const float* __restrict__ B,
                  float* __restrict__ C, int M)
{
    __shared__ float As[BK][BM];   // A tile transposed
    __shared__ float Bs[BK][BN];

    const int tid = threadIdx.x;                   // 0..255
    const int blockRow = blockIdx.x * BM;
    const int blockCol = blockIdx.y * BN;

    const int tcol = (tid & 15) * TN;              // 0..60
    const int trow = (tid >> 4) * TM;              // 0..120

    float acc[TM][TN];
#pragma unroll
    for (int i = 0; i < TM; i++)
#pragma unroll
        for (int j = 0; j < TN; j++) acc[i][j] = 0.f;

    for (int k0 = 0; k0 < D_IN; k0 += BK) {
        // --- load A tile (128 x 16): 512 float4, 2 per thread, transpose ---
#pragma unroll
        for (int it = 0; it < 2; it++) {
            int f  = tid + it * 256;       // 0..511
            int ar = f >> 2;               // 0..127 row within tile
            int ac = (f & 3) * 4;          // 0,4,8,12 col within tile
            int gr = blockRow + ar;
            float4 v;
            if (gr < M) {
                v = *reinterpret_cast<const float4*>(A + (size_t)gr * D_IN + k0 + ac);
            } else {
                v = make_float4(0.f, 0.f, 0.f, 0.f);
            }
            As[ac + 0][ar] = v.x;
            As[ac + 1][ar] = v.y;
            As[ac + 2][ar] = v.z;
            As[ac + 3][ar] = v.w;
        }
        // --- load B tile (16 x 64): 256 float4, 1 per thread ---
        {
            int br = tid >> 4;             // 0..15
            int bc = (tid & 15) * 4;       // 0..60
            float4 v = *reinterpret_cast<const float4*>(
                B + (size_t)(k0 + br) * D_OUT + blockCol + bc);
            *reinterpret_cast<float4*>(&Bs[br][bc]) = v;
        }
        __syncthreads();

#pragma unroll
        for (int k = 0; k < BK; k++) {
            float ra[TM], rb[TN];
#pragma unroll
            for (int i = 0; i < TM; i++) ra[i] = As[k][trow + i];
#pragma unroll
            for (int j = 0; j < TN; j++) rb[j] = Bs[k][tcol + j];
#pragma unroll
            for (int i = 0; i < TM; i++)
#pragma unroll
                for (int j = 0; j < TN; j++)
                    acc[i][j] = fmaf(ra[i], rb[j], acc[i][j]);
        }
        __syncthreads();
    }

    // --- store ---
#pragma unroll
    for (int i = 0; i < TM; i++) {
        int gr = blockRow + trow + i;
        if (gr < M) {
            float4 v = make_float4(acc[i][0], acc[i][1], acc[i][2], acc[i][3]);
            *reinterpret_cast<float4*>(C + (size_t)gr * D_OUT + blockCol + tcol) = v;
        }
    }
}

// ---------------------------------------------------------------------------
// Edge scatter: 16 threads per edge, each owns one float4 (4 of 64 chunk cols)
// zu[row, s*64 + 4*lane .. +3] += val * Yv[col, ...]
// zv[col, s*64 + 4*lane .. +3] += val * Yu[row, ...]
// Vector reduction: red.global.add.v4.f32 (sm_90+)
// ---------------------------------------------------------------------------
__device__ __forceinline__ void red_add_v4(float* addr, float4 v)
{
    asm volatile("red.global.add.v4.f32 [%0], {%1, %2, %3, %4};"
                 :: "l"(addr), "f"(v.x), "f"(v.y), "f"(v.z), "f"(v.w)
                 : "memory");
}

__global__ __launch_bounds__(256)
void scatter_kernel(const float* __restrict__ vals,
                    const int*   __restrict__ rows,
                    const int*   __restrict__ cols,
                    float* __restrict__ zu, float* __restrict__ zv)
{
    const long long t = (long long)blockIdx.x * blockDim.x + threadIdx.x;
    const int edge = (int)(t >> 4);
    const int lane = (int)(t & 15);
    if (edge >= S_REL * E_REL) return;

    const int s = edge / E_REL;
    const float val = __ldg(vals + edge);
    const int   r   = __ldg(rows + edge);
    const int   c   = __ldg(cols + edge);

    const int off = s * CHUNK + lane * 4;

    float4 yv = *reinterpret_cast<const float4*>(g_Yv + (size_t)c * D_OUT + off);
    float4 yu = *reinterpret_cast<const float4*>(g_Yu + (size_t)r * D_OUT + off);

    float4 au = make_float4(val * yv.x, val * yv.y, val * yv.z, val * yv.w);
    float4 av = make_float4(val * yu.x, val * yu.y, val * yu.z, val * yu.w);

    red_add_v4(zu + (size_t)r * D_OUT + off, au);
    red_add_v4(zv + (size_t)c * D_OUT + off, av);
}

// ---------------------------------------------------------------------------
// In-place ReLU on d_out
// ---------------------------------------------------------------------------
__global__ __launch_bounds__(256)
void relu_kernel(float4* __restrict__ p, long long n4)
{
    long long i = (long long)blockIdx.x * blockDim.x + threadIdx.x;
    long long stride = (long long)gridDim.x * blockDim.x;
    for (; i < n4; i += stride) {
        float4 v = p[i];
        v.x = fmaxf(v.x, 0.f);
        v.y = fmaxf(v.y, 0.f);
        v.z = fmaxf(v.z, 0.f);
        v.w = fmaxf(v.w, 0.f);
        p[i] = v;
    }
}

// ---------------------------------------------------------------------------
// Launch
// ---------------------------------------------------------------------------
extern "C" void kernel_launch(void* const* d_in, const int* in_sizes, int n_in,
                              void* d_out, int out_size)
{
    const float* x_u      = (const float*)d_in[0];  // [N_U, D_IN]
    const float* x_v      = (const float*)d_in[1];  // [N_V, D_IN]
    const float* W        = (const float*)d_in[2];  // [D_IN, D_OUT]
    const float* sup_vals = (const float*)d_in[3];  // [S, E]
    const int*   sup_rows = (const int*)  d_in[4];  // [S, E]
    const int*   sup_cols = (const int*)  d_in[5];  // [S, E]

    float* zu = (float*)d_out;                       // [N_U, D_OUT]
    float* zv = zu + (size_t)N_U * D_OUT;            // [N_V, D_OUT]

    // Scratch pointers (device symbols referenced directly by kernels;
    // need host-side address only for the GEMM output argument)
    float* dYu = nullptr;
    float* dYv = nullptr;
    cudaGetSymbolAddress((void**)&dYu, g_Yu);
    cudaGetSymbolAddress((void**)&dYv, g_Yv);

    // 1) GEMMs: Y = X @ W
    dim3 gemmBlock(256);
    dim3 gemmGridU((N_U + BM - 1) / BM, D_OUT / BN);
    dim3 gemmGridV((N_V + BM - 1) / BM, D_OUT / BN);
    sgemm_kernel<<<gemmGridU, gemmBlock>>>(x_u, W, dYu, N_U);
    sgemm_kernel<<<gemmGridV, gemmBlock>>>(x_v, W, dYv, N_V);

    // 2) zero accumulators (z lives in d_out)
    cudaMemsetAsync(d_out, 0, (size_t)out_size * sizeof(float), 0);

    // 3) edge scatter (both directions in one pass)
    {
        long long total = (long long)S_REL * E_REL * 16;   // 40,000,000 threads
        int threads = 256;
        long long blocks = (total + threads - 1) / threads;
        scatter_kernel<<<(unsigned)blocks, threads>>>(sup_vals, sup_rows, sup_cols,
                                                      zu, zv);
    }

    // 4) ReLU in place
    {
        long long n4 = (long long)out_size / 4;
        int threads = 256;
        int blocks = 4096;
        relu_kernel<<<blocks, threads>>>((float4*)d_out, n4);
    }
}

// round 5
// speedup vs baseline: 1.5957x; 1.5957x over previous
#include <cuda_runtime.h>
#include <cuda_bf16.h>
#include <cstdint>

// Problem constants (match reference)
#define N_U   100000
#define N_V   100000
#define D_IN  256
#define D_OUT 320
#define S_REL 5
#define E_REL 500000
#define CHUNK 64           // D_OUT / S_REL

// ---------------------------------------------------------------------------
// Scratch: Y_u = x_u @ W, Y_v = x_v @ W  (fp32, 128 MB each, static bss)
// ---------------------------------------------------------------------------
__device__ float g_Yu[(size_t)N_U * D_OUT];
__device__ float g_Yv[(size_t)N_V * D_OUT];

// ---------------------------------------------------------------------------
// TF32 tensor-core GEMM: C[M, 320] = A[M, 256] @ B[256, 320]
// BM=128, BN=64, BK=32; 256 threads = 8 warps in a 4(M) x 2(N) grid,
// each warp computes a 32x32 tile as 2x4 m16n8k8 mma fragments.
// Smem padded for conflict-free fragment loads.
// ---------------------------------------------------------------------------
#define GBM 128
#define GBN 64
#define GBK 32

__device__ __forceinline__ uint32_t f32_to_tf32(float x)
{
    uint32_t r;
    asm("cvt.rna.tf32.f32 %0, %1;" : "=r"(r) : "f"(x));
    return r;
}

__device__ __forceinline__ void mma_tf32(float c[4],
                                         uint32_t a0, uint32_t a1,
                                         uint32_t a2, uint32_t a3,
                                         uint32_t b0, uint32_t b1)
{
    asm volatile(
        "mma.sync.aligned.m16n8k8.row.col.f32.tf32.tf32.f32 "
        "{%0,%1,%2,%3}, {%4,%5,%6,%7}, {%8,%9}, {%0,%1,%2,%3};"
        : "+f"(c[0]), "+f"(c[1]), "+f"(c[2]), "+f"(c[3])
        : "r"(a0), "r"(a1), "r"(a2), "r"(a3), "r"(b0), "r"(b1));
}

__global__ __launch_bounds__(256)
void gemm_tf32_kernel(const float* __restrict__ A, const float* __restrict__ B,
                      float* __restrict__ C, int M)
{
    // Padded smem: As bank = (4*m + k) % 32, Bs bank = (8*k + n) % 32
    // -> fragment loads are permutations of banks 0..31 (conflict-free).
    __shared__ uint32_t As[GBM][GBK + 4];   // 128 x 36
    __shared__ uint32_t Bs[GBK][GBN + 8];   // 32 x 72

    const int tid  = threadIdx.x;
    const int lane = tid & 31;
    const int wid  = tid >> 5;          // 0..7
    const int warpM = wid & 3;          // 0..3  (M direction, 32 rows each)
    const int warpN = wid >> 2;         // 0..1  (N direction, 32 cols each)
    const int gid = lane >> 2;          // group id 0..7
    const int tig = lane & 3;           // thread-in-group 0..3

    const int blockRow = blockIdx.x * GBM;
    const int blockCol = blockIdx.y * GBN;

    float acc[2][4][4];
#pragma unroll
    for (int mi = 0; mi < 2; mi++)
#pragma unroll
        for (int ni = 0; ni < 4; ni++)
#pragma unroll
            for (int q = 0; q < 4; q++) acc[mi][ni][q] = 0.f;

    for (int kb = 0; kb < D_IN; kb += GBK) {
        // ---- load A tile (128 x 32 floats = 1024 float4, 4 per thread) ----
#pragma unroll
        for (int it = 0; it < 4; it++) {
            int f   = tid + it * 256;        // 0..1023
            int row = f >> 3;                // 0..127
            int col = (f & 7) * 4;           // 0..28
            int gr  = blockRow + row;
            float4 v = make_float4(0.f, 0.f, 0.f, 0.f);
            if (gr < M)
                v = *reinterpret_cast<const float4*>(A + (size_t)gr * D_IN + kb + col);
            uint4 t;
            t.x = f32_to_tf32(v.x);
            t.y = f32_to_tf32(v.y);
            t.z = f32_to_tf32(v.z);
            t.w = f32_to_tf32(v.w);
            *reinterpret_cast<uint4*>(&As[row][col]) = t;
        }
        // ---- load B tile (32 x 64 floats = 512 float4, 2 per thread) ----
#pragma unroll
        for (int it = 0; it < 2; it++) {
            int f   = tid + it * 256;        // 0..511
            int row = f >> 4;                // 0..31 (k)
            int col = (f & 15) * 4;          // 0..60 (n)
            float4 v = *reinterpret_cast<const float4*>(
                B + (size_t)(kb + row) * D_OUT + blockCol + col);
            uint4 t;
            t.x = f32_to_tf32(v.x);
            t.y = f32_to_tf32(v.y);
            t.z = f32_to_tf32(v.z);
            t.w = f32_to_tf32(v.w);
            *reinterpret_cast<uint4*>(&Bs[row][col]) = t;
        }
        __syncthreads();

        // ---- compute: 4 k8-steps, 8 mma each ----
#pragma unroll
        for (int kk = 0; kk < GBK; kk += 8) {
            uint32_t af[2][4];
#pragma unroll
            for (int mi = 0; mi < 2; mi++) {
                int rb = warpM * 32 + mi * 16 + gid;
                af[mi][0] = As[rb    ][kk + tig    ];
                af[mi][1] = As[rb + 8][kk + tig    ];
                af[mi][2] = As[rb    ][kk + tig + 4];
                af[mi][3] = As[rb + 8][kk + tig + 4];
            }
            uint32_t bf[4][2];
#pragma unroll
            for (int ni = 0; ni < 4; ni++) {
                int cb = warpN * 32 + ni * 8 + gid;
                bf[ni][0] = Bs[kk + tig    ][cb];
                bf[ni][1] = Bs[kk + tig + 4][cb];
            }
#pragma unroll
            for (int mi = 0; mi < 2; mi++)
#pragma unroll
                for (int ni = 0; ni < 4; ni++)
                    mma_tf32(acc[mi][ni],
                             af[mi][0], af[mi][1], af[mi][2], af[mi][3],
                             bf[ni][0], bf[ni][1]);
        }
        __syncthreads();
    }

    // ---- epilogue: c0,c1 at (row, 2*tig), c2,c3 at (row+8, 2*tig) ----
#pragma unroll
    for (int mi = 0; mi < 2; mi++) {
        int r0 = blockRow + warpM * 32 + mi * 16 + gid;
#pragma unroll
        for (int ni = 0; ni < 4; ni++) {
            int cc = blockCol + warpN * 32 + ni * 8 + tig * 2;
            if (r0 < M) {
                float2 v = make_float2(acc[mi][ni][0], acc[mi][ni][1]);
                *reinterpret_cast<float2*>(C + (size_t)r0 * D_OUT + cc) = v;
            }
            if (r0 + 8 < M) {
                float2 v = make_float2(acc[mi][ni][2], acc[mi][ni][3]);
                *reinterpret_cast<float2*>(C + (size_t)(r0 + 8) * D_OUT + cc) = v;
            }
        }
    }
}

// ---------------------------------------------------------------------------
// Edge scatter: 16 threads per edge, each owns one float4 (4 of 64 chunk cols)
// zu[row, s*64 + 4*lane .. +3] += val * Yv[col, ...]
// zv[col, s*64 + 4*lane .. +3] += val * Yu[row, ...]
// Vector reduction: red.global.add.v4.f32 (sm_90+)
// ---------------------------------------------------------------------------
__device__ __forceinline__ void red_add_v4(float* addr, float4 v)
{
    asm volatile("red.global.add.v4.f32 [%0], {%1, %2, %3, %4};"
                 :: "l"(addr), "f"(v.x), "f"(v.y), "f"(v.z), "f"(v.w)
                 : "memory");
}

__global__ __launch_bounds__(256)
void scatter_kernel(const float* __restrict__ vals,
                    const int*   __restrict__ rows,
                    const int*   __restrict__ cols,
                    float* __restrict__ zu, float* __restrict__ zv)
{
    const long long t = (long long)blockIdx.x * blockDim.x + threadIdx.x;
    const int edge = (int)(t >> 4);
    const int lane = (int)(t & 15);
    if (edge >= S_REL * E_REL) return;

    const int s = edge / E_REL;
    const float val = __ldg(vals + edge);
    const int   r   = __ldg(rows + edge);
    const int   c   = __ldg(cols + edge);

    const int off = s * CHUNK + lane * 4;

    float4 yv = *reinterpret_cast<const float4*>(g_Yv + (size_t)c * D_OUT + off);
    float4 yu = *reinterpret_cast<const float4*>(g_Yu + (size_t)r * D_OUT + off);

    float4 au = make_float4(val * yv.x, val * yv.y, val * yv.z, val * yv.w);
    float4 av = make_float4(val * yu.x, val * yu.y, val * yu.z, val * yu.w);

    red_add_v4(zu + (size_t)r * D_OUT + off, au);
    red_add_v4(zv + (size_t)c * D_OUT + off, av);
}

// ---------------------------------------------------------------------------
// In-place ReLU on d_out
// ---------------------------------------------------------------------------
__global__ __launch_bounds__(256)
void relu_kernel(float4* __restrict__ p, long long n4)
{
    long long i = (long long)blockIdx.x * blockDim.x + threadIdx.x;
    long long stride = (long long)gridDim.x * blockDim.x;
    for (; i < n4; i += stride) {
        float4 v = p[i];
        v.x = fmaxf(v.x, 0.f);
        v.y = fmaxf(v.y, 0.f);
        v.z = fmaxf(v.z, 0.f);
        v.w = fmaxf(v.w, 0.f);
        p[i] = v;
    }
}

// ---------------------------------------------------------------------------
// Launch
// ---------------------------------------------------------------------------
extern "C" void kernel_launch(void* const* d_in, const int* in_sizes, int n_in,
                              void* d_out, int out_size)
{
    const float* x_u      = (const float*)d_in[0];  // [N_U, D_IN]
    const float* x_v      = (const float*)d_in[1];  // [N_V, D_IN]
    const float* W        = (const float*)d_in[2];  // [D_IN, D_OUT]
    const float* sup_vals = (const float*)d_in[3];  // [S, E]
    const int*   sup_rows = (const int*)  d_in[4];  // [S, E]
    const int*   sup_cols = (const int*)  d_in[5];  // [S, E]

    float* zu = (float*)d_out;                       // [N_U, D_OUT]
    float* zv = zu + (size_t)N_U * D_OUT;            // [N_V, D_OUT]

    float* dYu = nullptr;
    float* dYv = nullptr;
    cudaGetSymbolAddress((void**)&dYu, g_Yu);
    cudaGetSymbolAddress((void**)&dYv, g_Yv);

    // 1) GEMMs on tensor cores (tf32): Y = X @ W
    dim3 gemmBlock(256);
    dim3 gemmGridU((N_U + GBM - 1) / GBM, D_OUT / GBN);
    dim3 gemmGridV((N_V + GBM - 1) / GBM, D_OUT / GBN);
    gemm_tf32_kernel<<<gemmGridU, gemmBlock>>>(x_u, W, dYu, N_U);
    gemm_tf32_kernel<<<gemmGridV, gemmBlock>>>(x_v, W, dYv, N_V);

    // 2) zero accumulators (z lives in d_out)
    cudaMemsetAsync(d_out, 0, (size_t)out_size * sizeof(float), 0);

    // 3) edge scatter (both directions in one pass)
    {
        long long total = (long long)S_REL * E_REL * 16;   // 40,000,000 threads
        int threads = 256;
        long long blocks = (total + threads - 1) / threads;
        scatter_kernel<<<(unsigned)blocks, threads>>>(sup_vals, sup_rows, sup_cols,
                                                      zu, zv);
    }

    // 4) ReLU in place
    {
        long long n4 = (long long)out_size / 4;
        int threads = 256;
        int blocks = 4096;
        relu_kernel<<<blocks, threads>>>((float4*)d_out, n4);
    }
}

// round 6
// speedup vs baseline: 1.7083x; 1.0705x over previous
#include <cuda_runtime.h>
#include <cuda_bf16.h>
#include <cstdint>

// Problem constants (match reference)
#define N_U   100000
#define N_V   100000
#define D_IN  256
#define D_OUT 320
#define S_REL 5
#define E_REL 500000
#define CHUNK 64                    // D_OUT / S_REL
#define TOT_E (S_REL * E_REL)       // 2,500,000
#define SEG   (S_REL * N_U)         // 500,000 segments per side
#define NBLK  ((SEG + 1023) / 1024) // 489 scan blocks

// ---------------------------------------------------------------------------
// Scratch (static bss; no allocations)
// ---------------------------------------------------------------------------
__device__ float g_Yu[(size_t)N_U * D_OUT];   // x_u @ W
__device__ float g_Yv[(size_t)N_V * D_OUT];   // x_v @ W
__device__ int   g_off_u[SEG];                // per-(s,row) counts -> offsets -> ends
__device__ int   g_off_v[SEG];                // per-(s,col)
__device__ int2  g_eu[TOT_E];                 // records for zu: (col, val-bits)
__device__ int2  g_ev[TOT_E];                 // records for zv: (row, val-bits)
__device__ int   g_bsum[2][512];              // scan block sums

// ---------------------------------------------------------------------------
// TF32 tensor-core GEMM: C[M, 320] = A[M, 256] @ B[256, 320]
// ---------------------------------------------------------------------------
#define GBM 128
#define GBN 64
#define GBK 32

__device__ __forceinline__ uint32_t f32_to_tf32(float x)
{
    uint32_t r;
    asm("cvt.rna.tf32.f32 %0, %1;" : "=r"(r) : "f"(x));
    return r;
}

__device__ __forceinline__ void mma_tf32(float c[4],
                                         uint32_t a0, uint32_t a1,
                                         uint32_t a2, uint32_t a3,
                                         uint32_t b0, uint32_t b1)
{
    asm volatile(
        "mma.sync.aligned.m16n8k8.row.col.f32.tf32.tf32.f32 "
        "{%0,%1,%2,%3}, {%4,%5,%6,%7}, {%8,%9}, {%0,%1,%2,%3};"
        : "+f"(c[0]), "+f"(c[1]), "+f"(c[2]), "+f"(c[3])
        : "r"(a0), "r"(a1), "r"(a2), "r"(a3), "r"(b0), "r"(b1));
}

__global__ __launch_bounds__(256)
void gemm_tf32_kernel(const float* __restrict__ A, const float* __restrict__ B,
                      float* __restrict__ C, int M)
{
    __shared__ uint32_t As[GBM][GBK + 4];   // 128 x 36
    __shared__ uint32_t Bs[GBK][GBN + 8];   // 32 x 72

    const int tid  = threadIdx.x;
    const int lane = tid & 31;
    const int wid  = tid >> 5;
    const int warpM = wid & 3;
    const int warpN = wid >> 2;
    const int gid = lane >> 2;
    const int tig = lane & 3;

    const int blockRow = blockIdx.x * GBM;
    const int blockCol = blockIdx.y * GBN;

    float acc[2][4][4];
#pragma unroll
    for (int mi = 0; mi < 2; mi++)
#pragma unroll
        for (int ni = 0; ni < 4; ni++)
#pragma unroll
            for (int q = 0; q < 4; q++) acc[mi][ni][q] = 0.f;

    for (int kb = 0; kb < D_IN; kb += GBK) {
#pragma unroll
        for (int it = 0; it < 4; it++) {
            int f   = tid + it * 256;
            int row = f >> 3;
            int col = (f & 7) * 4;
            int gr  = blockRow + row;
            float4 v = make_float4(0.f, 0.f, 0.f, 0.f);
            if (gr < M)
                v = *reinterpret_cast<const float4*>(A + (size_t)gr * D_IN + kb + col);
            uint4 t;
            t.x = f32_to_tf32(v.x);
            t.y = f32_to_tf32(v.y);
            t.z = f32_to_tf32(v.z);
            t.w = f32_to_tf32(v.w);
            *reinterpret_cast<uint4*>(&As[row][col]) = t;
        }
#pragma unroll
        for (int it = 0; it < 2; it++) {
            int f   = tid + it * 256;
            int row = f >> 4;
            int col = (f & 15) * 4;
            float4 v = *reinterpret_cast<const float4*>(
                B + (size_t)(kb + row) * D_OUT + blockCol + col);
            uint4 t;
            t.x = f32_to_tf32(v.x);
            t.y = f32_to_tf32(v.y);
            t.z = f32_to_tf32(v.z);
            t.w = f32_to_tf32(v.w);
            *reinterpret_cast<uint4*>(&Bs[row][col]) = t;
        }
        __syncthreads();

#pragma unroll
        for (int kk = 0; kk < GBK; kk += 8) {
            uint32_t af[2][4];
#pragma unroll
            for (int mi = 0; mi < 2; mi++) {
                int rb = warpM * 32 + mi * 16 + gid;
                af[mi][0] = As[rb    ][kk + tig    ];
                af[mi][1] = As[rb + 8][kk + tig    ];
                af[mi][2] = As[rb    ][kk + tig + 4];
                af[mi][3] = As[rb + 8][kk + tig + 4];
            }
            uint32_t bf[4][2];
#pragma unroll
            for (int ni = 0; ni < 4; ni++) {
                int cb = warpN * 32 + ni * 8 + gid;
                bf[ni][0] = Bs[kk + tig    ][cb];
                bf[ni][1] = Bs[kk + tig + 4][cb];
            }
#pragma unroll
            for (int mi = 0; mi < 2; mi++)
#pragma unroll
                for (int ni = 0; ni < 4; ni++)
                    mma_tf32(acc[mi][ni],
                             af[mi][0], af[mi][1], af[mi][2], af[mi][3],
                             bf[ni][0], bf[ni][1]);
        }
        __syncthreads();
    }

#pragma unroll
    for (int mi = 0; mi < 2; mi++) {
        int r0 = blockRow + warpM * 32 + mi * 16 + gid;
#pragma unroll
        for (int ni = 0; ni < 4; ni++) {
            int cc = blockCol + warpN * 32 + ni * 8 + tig * 2;
            if (r0 < M) {
                float2 v = make_float2(acc[mi][ni][0], acc[mi][ni][1]);
                *reinterpret_cast<float2*>(C + (size_t)r0 * D_OUT + cc) = v;
            }
            if (r0 + 8 < M) {
                float2 v = make_float2(acc[mi][ni][2], acc[mi][ni][3]);
                *reinterpret_cast<float2*>(C + (size_t)(r0 + 8) * D_OUT + cc) = v;
            }
        }
    }
}

// ---------------------------------------------------------------------------
// CSR build step 1: histogram per (s, row) and (s, col) segment
// ---------------------------------------------------------------------------
__global__ __launch_bounds__(256)
void hist_kernel(const int* __restrict__ rows, const int* __restrict__ cols)
{
    int e = blockIdx.x * blockDim.x + threadIdx.x;
    if (e >= TOT_E) return;
    int s = e / E_REL;
    int r = __ldg(rows + e);
    int c = __ldg(cols + e);
    atomicAdd(&g_off_u[s * N_U + r], 1);
    atomicAdd(&g_off_v[s * N_V + c], 1);
}

// ---------------------------------------------------------------------------
// CSR build step 2: two-level exclusive scan over 500k counters (both sides)
// ---------------------------------------------------------------------------
__global__ __launch_bounds__(1024)
void scan1_kernel()
{
    __shared__ int sh[1024];
    int* buf = blockIdx.y ? g_off_v : g_off_u;
    int tid = threadIdx.x;
    int gid = blockIdx.x * 1024 + tid;
    int v = (gid < SEG) ? buf[gid] : 0;
    sh[tid] = v;
    __syncthreads();
#pragma unroll
    for (int d = 1; d < 1024; d <<= 1) {
        int t = (tid >= d) ? sh[tid - d] : 0;
        __syncthreads();
        sh[tid] += t;
        __syncthreads();
    }
    if (gid < SEG) buf[gid] = sh[tid] - v;     // exclusive
    if (tid == 1023) g_bsum[blockIdx.y][blockIdx.x] = sh[1023];
}

__global__ __launch_bounds__(512)
void scan2_kernel()
{
    __shared__ int sh[512];
    int tid = threadIdx.x;
    int side = blockIdx.y;
    int v = (tid < NBLK) ? g_bsum[side][tid] : 0;
    sh[tid] = v;
    __syncthreads();
#pragma unroll
    for (int d = 1; d < 512; d <<= 1) {
        int t = (tid >= d) ? sh[tid - d] : 0;
        __syncthreads();
        sh[tid] += t;
        __syncthreads();
    }
    if (tid < NBLK) g_bsum[side][tid] = sh[tid] - v;  // exclusive
}

__global__ __launch_bounds__(1024)
void scan3_kernel()
{
    int* buf = blockIdx.y ? g_off_v : g_off_u;
    int gid = blockIdx.x * 1024 + threadIdx.x;
    if (gid < SEG) buf[gid] += g_bsum[blockIdx.y][blockIdx.x];
}

// ---------------------------------------------------------------------------
// CSR build step 3: fill packed (index, val) records in segment order.
// Uses atomicAdd on the offsets themselves; afterwards g_off_*[seg] holds the
// END of segment seg (start = g_off_*[seg-1], or 0 for seg 0).
// ---------------------------------------------------------------------------
__global__ __launch_bounds__(256)
void fill_kernel(const float* __restrict__ vals,
                 const int*   __restrict__ rows,
                 const int*   __restrict__ cols)
{
    int e = blockIdx.x * blockDim.x + threadIdx.x;
    if (e >= TOT_E) return;
    int s = e / E_REL;
    int r = __ldg(rows + e);
    int c = __ldg(cols + e);
    int vb = __float_as_int(__ldg(vals + e));

    int pu = atomicAdd(&g_off_u[s * N_U + r], 1);
    g_eu[pu] = make_int2(c, vb);
    int pv = atomicAdd(&g_off_v[s * N_V + c], 1);
    g_ev[pv] = make_int2(r, vb);
}

// ---------------------------------------------------------------------------
// Gather: 16 threads per (s, out_row) segment, each owns one float4 of the
// 64-wide chunk. Accumulate in registers, write once with fused ReLU.
// side 0: zu from Yv via g_eu;  side 1: zv from Yu via g_ev.
// ---------------------------------------------------------------------------
__global__ __launch_bounds__(128)
void gather_kernel(float* __restrict__ zu, float* __restrict__ zv)
{
    const int side = blockIdx.y;
    const long long t = (long long)blockIdx.x * 128 + threadIdx.x;
    const int seg  = (int)(t >> 4);
    const int lane = (int)(t & 15);
    if (seg >= SEG) return;

    const int s = seg / N_U;            // N_U == N_V
    const int orow = seg - s * N_U;
    const int off = s * CHUNK + lane * 4;

    const int2*  recs = side ? g_ev : g_eu;
    const float* Y    = side ? g_Yu : g_Yv;
    float*       out  = side ? zv   : zu;
    const int*   ends = side ? g_off_v : g_off_u;

    const int end = __ldg(ends + seg);
    const int beg = seg ? __ldg(ends + seg - 1) : 0;

    float4 acc = make_float4(0.f, 0.f, 0.f, 0.f);
    for (int e = beg; e < end; e++) {
        int2 rec = __ldg(recs + e);                     // broadcast across 16 lanes
        float val = __int_as_float(rec.y);
        float4 y = *reinterpret_cast<const float4*>(Y + (size_t)rec.x * D_OUT + off);
        acc.x = fmaf(val, y.x, acc.x);
        acc.y = fmaf(val, y.y, acc.y);
        acc.z = fmaf(val, y.z, acc.z);
        acc.w = fmaf(val, y.w, acc.w);
    }
    acc.x = fmaxf(acc.x, 0.f);
    acc.y = fmaxf(acc.y, 0.f);
    acc.z = fmaxf(acc.z, 0.f);
    acc.w = fmaxf(acc.w, 0.f);
    *reinterpret_cast<float4*>(out + (size_t)orow * D_OUT + off) = acc;
}

// ---------------------------------------------------------------------------
// Launch
// ---------------------------------------------------------------------------
extern "C" void kernel_launch(void* const* d_in, const int* in_sizes, int n_in,
                              void* d_out, int out_size)
{
    const float* x_u      = (const float*)d_in[0];  // [N_U, D_IN]
    const float* x_v      = (const float*)d_in[1];  // [N_V, D_IN]
    const float* W        = (const float*)d_in[2];  // [D_IN, D_OUT]
    const float* sup_vals = (const float*)d_in[3];  // [S, E]
    const int*   sup_rows = (const int*)  d_in[4];  // [S, E]
    const int*   sup_cols = (const int*)  d_in[5];  // [S, E]

    float* zu = (float*)d_out;                       // [N_U, D_OUT]
    float* zv = zu + (size_t)N_U * D_OUT;            // [N_V, D_OUT]

    float* dYu = nullptr;
    float* dYv = nullptr;
    void*  dOffU = nullptr;
    void*  dOffV = nullptr;
    cudaGetSymbolAddress((void**)&dYu, g_Yu);
    cudaGetSymbolAddress((void**)&dYv, g_Yv);
    cudaGetSymbolAddress(&dOffU, g_off_u);
    cudaGetSymbolAddress(&dOffV, g_off_v);

    // 1) GEMMs on tensor cores (tf32): Y = X @ W
    dim3 gemmBlock(256);
    dim3 gemmGridU((N_U + GBM - 1) / GBM, D_OUT / GBN);
    dim3 gemmGridV((N_V + GBM - 1) / GBM, D_OUT / GBN);
    gemm_tf32_kernel<<<gemmGridU, gemmBlock>>>(x_u, W, dYu, N_U);
    gemm_tf32_kernel<<<gemmGridV, gemmBlock>>>(x_v, W, dYv, N_V);

    // 2) CSR build (independent of GEMMs, same stream)
    cudaMemsetAsync(dOffU, 0, SEG * sizeof(int), 0);
    cudaMemsetAsync(dOffV, 0, SEG * sizeof(int), 0);

    {
        int threads = 256;
        int blocks = (TOT_E + threads - 1) / threads;
        hist_kernel<<<blocks, threads>>>(sup_rows, sup_cols);
    }
    {
        dim3 g1(NBLK, 2);
        scan1_kernel<<<g1, 1024>>>();
        dim3 g2(1, 2);
        scan2_kernel<<<g2, 512>>>();
        dim3 g3(NBLK, 2);
        scan3_kernel<<<g3, 1024>>>();
    }
    {
        int threads = 256;
        int blocks = (TOT_E + threads - 1) / threads;
        fill_kernel<<<blocks, threads>>>(sup_vals, sup_rows, sup_cols);
    }

    // 3) Gather with fused ReLU (no memset, no atomics on output)
    {
        long long total = (long long)SEG * 16;
        dim3 grid((unsigned)((total + 127) / 128), 2);
        gather_kernel<<<grid, 128>>>(zu, zv);
    }
}

// round 8
// speedup vs baseline: 1.8520x; 1.0842x over previous
#include <cuda_runtime.h>
#include <cuda_bf16.h>
#include <cstdint>

// Problem constants (match reference)
#define N_U   100000
#define N_V   100000
#define D_IN  256
#define D_OUT 320
#define S_REL 5
#define E_REL 500000
#define CHUNK 64                    // D_OUT / S_REL
#define TOT_E (S_REL * E_REL)       // 2,500,000
#define SEG   (S_REL * N_U)         // 500,000 segments per side
#define NBLK  ((SEG + 1023) / 1024) // 489 scan blocks

// ---------------------------------------------------------------------------
// Scratch (static bss; no allocations)
// ---------------------------------------------------------------------------
__device__ float g_Yu[(size_t)N_U * D_OUT];   // x_u @ W
__device__ float g_Yv[(size_t)N_V * D_OUT];   // x_v @ W
__device__ int   g_off_u[SEG];                // per-(s,row) counts -> offsets -> ends
__device__ int   g_off_v[SEG];                // per-(s,col)
__device__ int2  g_eu[TOT_E];                 // records for zu: (col, val-bits)
__device__ int2  g_ev[TOT_E];                 // records for zv: (row, val-bits)
__device__ int   g_bsum[2][512];              // scan block sums

// ---------------------------------------------------------------------------
// TF32 tensor-core GEMM: C[M, 320] = A[M, 256] @ B[256, 320]
// Double-buffered DYNAMIC smem (55.3 KB > 48 KB static limit), register-staged
// global prefetch. gridDim.z selects (A, C) pair so both GEMMs run in one
// launch.
// ---------------------------------------------------------------------------
#define GBM 128
#define GBN 64
#define GBK 32
#define KSTEPS (D_IN / GBK)   // 8

#define AS_STRIDE (GBK + 4)                         // 36
#define BS_STRIDE (GBN + 8)                         // 72
#define AS_WORDS  (GBM * AS_STRIDE)                 // 4608 per buffer
#define BS_WORDS  (GBK * BS_STRIDE)                 // 2304 per buffer
#define GEMM_SMEM_BYTES ((2 * AS_WORDS + 2 * BS_WORDS) * 4)   // 55296

__device__ __forceinline__ uint32_t f32_to_tf32(float x)
{
    uint32_t r;
    asm("cvt.rna.tf32.f32 %0, %1;" : "=r"(r) : "f"(x));
    return r;
}

__device__ __forceinline__ void mma_tf32(float c[4],
                                         uint32_t a0, uint32_t a1,
                                         uint32_t a2, uint32_t a3,
                                         uint32_t b0, uint32_t b1)
{
    asm volatile(
        "mma.sync.aligned.m16n8k8.row.col.f32.tf32.tf32.f32 "
        "{%0,%1,%2,%3}, {%4,%5,%6,%7}, {%8,%9}, {%0,%1,%2,%3};"
        : "+f"(c[0]), "+f"(c[1]), "+f"(c[2]), "+f"(c[3])
        : "r"(a0), "r"(a1), "r"(a2), "r"(a3), "r"(b0), "r"(b1));
}

__global__ __launch_bounds__(256)
void gemm_tf32_kernel(const float* __restrict__ Au, const float* __restrict__ Av,
                      const float* __restrict__ B,
                      float* __restrict__ Cu, float* __restrict__ Cv, int M)
{
    // Padded smem: As bank = (4*m + k) % 32, Bs bank = (8*k + n) % 32
    // -> fragment loads are permutations of banks 0..31 (conflict-free).
    extern __shared__ uint32_t dynsmem[];
    uint32_t* AsBuf[2] = { dynsmem, dynsmem + AS_WORDS };
    uint32_t* BsBuf[2] = { dynsmem + 2 * AS_WORDS,
                           dynsmem + 2 * AS_WORDS + BS_WORDS };

    const float* A = blockIdx.z ? Av : Au;
    float*       C = blockIdx.z ? Cv : Cu;

    const int tid  = threadIdx.x;
    const int lane = tid & 31;
    const int wid  = tid >> 5;
    const int warpM = wid & 3;
    const int warpN = wid >> 2;
    const int gid = lane >> 2;
    const int tig = lane & 3;

    const int blockRow = blockIdx.x * GBM;
    const int blockCol = blockIdx.y * GBN;

    float acc[2][4][4];
#pragma unroll
    for (int mi = 0; mi < 2; mi++)
#pragma unroll
        for (int ni = 0; ni < 4; ni++)
#pragma unroll
            for (int q = 0; q < 4; q++) acc[mi][ni][q] = 0.f;

    float4 aReg[4];
    float4 bReg[2];

    // ---- global load of K-step kb into registers ----
    auto load_tile = [&](int kb) {
#pragma unroll
        for (int it = 0; it < 4; it++) {
            int f   = tid + it * 256;        // 0..1023
            int row = f >> 3;                // 0..127
            int col = (f & 7) * 4;           // 0..28
            int gr  = blockRow + row;
            aReg[it] = make_float4(0.f, 0.f, 0.f, 0.f);
            if (gr < M)
                aReg[it] = *reinterpret_cast<const float4*>(
                    A + (size_t)gr * D_IN + kb * GBK + col);
        }
#pragma unroll
        for (int it = 0; it < 2; it++) {
            int f   = tid + it * 256;        // 0..511
            int row = f >> 4;                // 0..31 (k)
            int col = (f & 15) * 4;          // 0..60 (n)
            bReg[it] = *reinterpret_cast<const float4*>(
                B + (size_t)(kb * GBK + row) * D_OUT + blockCol + col);
        }
    };

    // ---- store registers into smem buffer `buf` (with tf32 convert) ----
    auto store_tile = [&](int buf) {
        uint32_t* As = AsBuf[buf];
        uint32_t* Bs = BsBuf[buf];
#pragma unroll
        for (int it = 0; it < 4; it++) {
            int f   = tid + it * 256;
            int row = f >> 3;
            int col = (f & 7) * 4;
            uint4 t;
            t.x = f32_to_tf32(aReg[it].x);
            t.y = f32_to_tf32(aReg[it].y);
            t.z = f32_to_tf32(aReg[it].z);
            t.w = f32_to_tf32(aReg[it].w);
            *reinterpret_cast<uint4*>(&As[row * AS_STRIDE + col]) = t;
        }
#pragma unroll
        for (int it = 0; it < 2; it++) {
            int f   = tid + it * 256;
            int row = f >> 4;
            int col = (f & 15) * 4;
            uint4 t;
            t.x = f32_to_tf32(bReg[it].x);
            t.y = f32_to_tf32(bReg[it].y);
            t.z = f32_to_tf32(bReg[it].z);
            t.w = f32_to_tf32(bReg[it].w);
            *reinterpret_cast<uint4*>(&Bs[row * BS_STRIDE + col]) = t;
        }
    };

    auto compute_tile = [&](int buf) {
        const uint32_t* As = AsBuf[buf];
        const uint32_t* Bs = BsBuf[buf];
#pragma unroll
        for (int kk = 0; kk < GBK; kk += 8) {
            uint32_t af[2][4];
#pragma unroll
            for (int mi = 0; mi < 2; mi++) {
                int rb = warpM * 32 + mi * 16 + gid;
                af[mi][0] = As[(rb    ) * AS_STRIDE + kk + tig    ];
                af[mi][1] = As[(rb + 8) * AS_STRIDE + kk + tig    ];
                af[mi][2] = As[(rb    ) * AS_STRIDE + kk + tig + 4];
                af[mi][3] = As[(rb + 8) * AS_STRIDE + kk + tig + 4];
            }
            uint32_t bf[4][2];
#pragma unroll
            for (int ni = 0; ni < 4; ni++) {
                int cb = warpN * 32 + ni * 8 + gid;
                bf[ni][0] = Bs[(kk + tig    ) * BS_STRIDE + cb];
                bf[ni][1] = Bs[(kk + tig + 4) * BS_STRIDE + cb];
            }
#pragma unroll
            for (int mi = 0; mi < 2; mi++)
#pragma unroll
                for (int ni = 0; ni < 4; ni++)
                    mma_tf32(acc[mi][ni],
                             af[mi][0], af[mi][1], af[mi][2], af[mi][3],
                             bf[ni][0], bf[ni][1]);
        }
    };

    // ---- pipeline: prologue ----
    load_tile(0);
    store_tile(0);
    __syncthreads();

#pragma unroll
    for (int kb = 0; kb < KSTEPS; kb++) {
        if (kb + 1 < KSTEPS)
            load_tile(kb + 1);          // LDGs in flight during compute
        compute_tile(kb & 1);
        if (kb + 1 < KSTEPS) {
            store_tile((kb + 1) & 1);   // other buffer: safe vs current compute
            __syncthreads();
        }
    }

    // ---- epilogue ----
#pragma unroll
    for (int mi = 0; mi < 2; mi++) {
        int r0 = blockRow + warpM * 32 + mi * 16 + gid;
#pragma unroll
        for (int ni = 0; ni < 4; ni++) {
            int cc = blockCol + warpN * 32 + ni * 8 + tig * 2;
            if (r0 < M) {
                float2 v = make_float2(acc[mi][ni][0], acc[mi][ni][1]);
                *reinterpret_cast<float2*>(C + (size_t)r0 * D_OUT + cc) = v;
            }
            if (r0 + 8 < M) {
                float2 v = make_float2(acc[mi][ni][2], acc[mi][ni][3]);
                *reinterpret_cast<float2*>(C + (size_t)(r0 + 8) * D_OUT + cc) = v;
            }
        }
    }
}

// ---------------------------------------------------------------------------
// CSR build step 1: histogram per (s, row) and (s, col) segment
// ---------------------------------------------------------------------------
__global__ __launch_bounds__(256)
void hist_kernel(const int* __restrict__ rows, const int* __restrict__ cols)
{
    int e = blockIdx.x * blockDim.x + threadIdx.x;
    if (e >= TOT_E) return;
    int s = e / E_REL;
    int r = __ldg(rows + e);
    int c = __ldg(cols + e);
    atomicAdd(&g_off_u[s * N_U + r], 1);
    atomicAdd(&g_off_v[s * N_V + c], 1);
}

// ---------------------------------------------------------------------------
// CSR build step 2: two-level exclusive scan over 500k counters (both sides)
// ---------------------------------------------------------------------------
__global__ __launch_bounds__(1024)
void scan1_kernel()
{
    __shared__ int sh[1024];
    int* buf = blockIdx.y ? g_off_v : g_off_u;
    int tid = threadIdx.x;
    int gid = blockIdx.x * 1024 + tid;
    int v = (gid < SEG) ? buf[gid] : 0;
    sh[tid] = v;
    __syncthreads();
#pragma unroll
    for (int d = 1; d < 1024; d <<= 1) {
        int t = (tid >= d) ? sh[tid - d] : 0;
        __syncthreads();
        sh[tid] += t;
        __syncthreads();
    }
    if (gid < SEG) buf[gid] = sh[tid] - v;     // exclusive
    if (tid == 1023) g_bsum[blockIdx.y][blockIdx.x] = sh[1023];
}

__global__ __launch_bounds__(512)
void scan2_kernel()
{
    __shared__ int sh[512];
    int tid = threadIdx.x;
    int side = blockIdx.y;
    int v = (tid < NBLK) ? g_bsum[side][tid] : 0;
    sh[tid] = v;
    __syncthreads();
#pragma unroll
    for (int d = 1; d < 512; d <<= 1) {
        int t = (tid >= d) ? sh[tid - d] : 0;
        __syncthreads();
        sh[tid] += t;
        __syncthreads();
    }
    if (tid < NBLK) g_bsum[side][tid] = sh[tid] - v;  // exclusive
}

__global__ __launch_bounds__(1024)
void scan3_kernel()
{
    int* buf = blockIdx.y ? g_off_v : g_off_u;
    int gid = blockIdx.x * 1024 + threadIdx.x;
    if (gid < SEG) buf[gid] += g_bsum[blockIdx.y][blockIdx.x];
}

// ---------------------------------------------------------------------------
// CSR build step 3: fill packed (index, val) records in segment order.
// Afterwards g_off_*[seg] holds the END of segment seg.
// ---------------------------------------------------------------------------
__global__ __launch_bounds__(256)
void fill_kernel(const float* __restrict__ vals,
                 const int*   __restrict__ rows,
                 const int*   __restrict__ cols)
{
    int e = blockIdx.x * blockDim.x + threadIdx.x;
    if (e >= TOT_E) return;
    int s = e / E_REL;
    int r = __ldg(rows + e);
    int c = __ldg(cols + e);
    int vb = __float_as_int(__ldg(vals + e));

    int pu = atomicAdd(&g_off_u[s * N_U + r], 1);
    g_eu[pu] = make_int2(c, vb);
    int pv = atomicAdd(&g_off_v[s * N_V + c], 1);
    g_ev[pv] = make_int2(r, vb);
}

// ---------------------------------------------------------------------------
// Gather: 16 threads per (s, out_row) segment, each owns one float4 of the
// 64-wide chunk. Edge loop unrolled x2 for MLP. Write once with fused ReLU.
// ---------------------------------------------------------------------------
__global__ __launch_bounds__(256)
void gather_kernel(float* __restrict__ zu, float* __restrict__ zv)
{
    const int side = blockIdx.y;
    const long long t = (long long)blockIdx.x * 256 + threadIdx.x;
    const int seg  = (int)(t >> 4);
    const int lane = (int)(t & 15);
    if (seg >= SEG) return;

    const int s = seg / N_U;            // N_U == N_V
    const int orow = seg - s * N_U;
    const int off = s * CHUNK + lane * 4;

    const int2*  recs = side ? g_ev : g_eu;
    const float* Y    = side ? g_Yu : g_Yv;
    float*       out  = side ? zv   : zu;
    const int*   ends = side ? g_off_v : g_off_u;

    const int end = __ldg(ends + seg);
    int e = seg ? __ldg(ends + seg - 1) : 0;

    float4 acc = make_float4(0.f, 0.f, 0.f, 0.f);
    for (; e + 2 <= end; e += 2) {
        int2 r0 = __ldg(recs + e);
        int2 r1 = __ldg(recs + e + 1);
        float v0 = __int_as_float(r0.y);
        float v1 = __int_as_float(r1.y);
        float4 y0 = *reinterpret_cast<const float4*>(Y + (size_t)r0.x * D_OUT + off);
        float4 y1 = *reinterpret_cast<const float4*>(Y + (size_t)r1.x * D_OUT + off);
        acc.x = fmaf(v0, y0.x, acc.x);  acc.x = fmaf(v1, y1.x, acc.x);
        acc.y = fmaf(v0, y0.y, acc.y);  acc.y = fmaf(v1, y1.y, acc.y);
        acc.z = fmaf(v0, y0.z, acc.z);  acc.z = fmaf(v1, y1.z, acc.z);
        acc.w = fmaf(v0, y0.w, acc.w);  acc.w = fmaf(v1, y1.w, acc.w);
    }
    if (e < end) {
        int2 rec = __ldg(recs + e);
        float val = __int_as_float(rec.y);
        float4 y = *reinterpret_cast<const float4*>(Y + (size_t)rec.x * D_OUT + off);
        acc.x = fmaf(val, y.x, acc.x);
        acc.y = fmaf(val, y.y, acc.y);
        acc.z = fmaf(val, y.z, acc.z);
        acc.w = fmaf(val, y.w, acc.w);
    }
    acc.x = fmaxf(acc.x, 0.f);
    acc.y = fmaxf(acc.y, 0.f);
    acc.z = fmaxf(acc.z, 0.f);
    acc.w = fmaxf(acc.w, 0.f);
    *reinterpret_cast<float4*>(out + (size_t)orow * D_OUT + off) = acc;
}

// ---------------------------------------------------------------------------
// Launch: GEMMs on the main stream, CSR build concurrently on a side stream
// (event fork/join — graph-capture legal), gather after the join.
// kernel_launch is only invoked for the correctness run and the single
// capture call, so leaking one stream + two events per call is harmless and
// keeps every call's captured work identical.
// ---------------------------------------------------------------------------
extern "C" void kernel_launch(void* const* d_in, const int* in_sizes, int n_in,
                              void* d_out, int out_size)
{
    const float* x_u      = (const float*)d_in[0];  // [N_U, D_IN]
    const float* x_v      = (const float*)d_in[1];  // [N_V, D_IN]
    const float* W        = (const float*)d_in[2];  // [D_IN, D_OUT]
    const float* sup_vals = (const float*)d_in[3];  // [S, E]
    const int*   sup_rows = (const int*)  d_in[4];  // [S, E]
    const int*   sup_cols = (const int*)  d_in[5];  // [S, E]

    float* zu = (float*)d_out;                       // [N_U, D_OUT]
    float* zv = zu + (size_t)N_U * D_OUT;            // [N_V, D_OUT]

    float* dYu = nullptr;
    float* dYv = nullptr;
    void*  dOffU = nullptr;
    void*  dOffV = nullptr;
    cudaGetSymbolAddress((void**)&dYu, g_Yu);
    cudaGetSymbolAddress((void**)&dYv, g_Yv);
    cudaGetSymbolAddress(&dOffU, g_off_u);
    cudaGetSymbolAddress(&dOffV, g_off_v);

    // opt-in to >48KB dynamic smem for the GEMM (function attribute, no alloc)
    cudaFuncSetAttribute(gemm_tf32_kernel,
                         cudaFuncAttributeMaxDynamicSharedMemorySize,
                         GEMM_SMEM_BYTES);

    cudaStream_t s2;
    cudaEvent_t evFork, evJoin;
    cudaStreamCreateWithFlags(&s2, cudaStreamNonBlocking);
    cudaEventCreateWithFlags(&evFork, cudaEventDisableTiming);
    cudaEventCreateWithFlags(&evJoin, cudaEventDisableTiming);

    // fork side stream from the main stream
    cudaEventRecord(evFork, 0);
    cudaStreamWaitEvent(s2, evFork, 0);

    // --- main stream: both GEMMs in one launch (tensor pipe) ---
    {
        dim3 grid((N_U + GBM - 1) / GBM, D_OUT / GBN, 2);
        gemm_tf32_kernel<<<grid, 256, GEMM_SMEM_BYTES>>>(x_u, x_v, W, dYu, dYv, N_U);
    }

    // --- side stream: CSR build (LSU / L2-atomic pipe) ---
    cudaMemsetAsync(dOffU, 0, SEG * sizeof(int), s2);
    cudaMemsetAsync(dOffV, 0, SEG * sizeof(int), s2);
    {
        int threads = 256;
        int blocks = (TOT_E + threads - 1) / threads;
        hist_kernel<<<blocks, threads, 0, s2>>>(sup_rows, sup_cols);
        dim3 g1(NBLK, 2);
        scan1_kernel<<<g1, 1024, 0, s2>>>();
        dim3 g2(1, 2);
        scan2_kernel<<<g2, 512, 0, s2>>>();
        dim3 g3(NBLK, 2);
        scan3_kernel<<<g3, 1024, 0, s2>>>();
        fill_kernel<<<blocks, threads, 0, s2>>>(sup_vals, sup_rows, sup_cols);
    }

    // join side stream back into the main stream
    cudaEventRecord(evJoin, s2);
    cudaStreamWaitEvent(0, evJoin, 0);

    // --- gather with fused ReLU (needs GEMM results + CSR) ---
    {
        long long total = (long long)SEG * 16;
        dim3 grid((unsigned)((total + 255) / 256), 2);
        gather_kernel<<<grid, 256>>>(zu, zv);
    }
}

// round 11
// speedup vs baseline: 2.0848x; 1.1257x over previous
#include <cuda_runtime.h>
#include <cuda_fp16.h>
#include <cstdint>

// Problem constants (match reference)
#define N_U   100000
#define N_V   100000
#define D_IN  256
#define D_OUT 320
#define S_REL 5
#define E_REL 500000
#define CHUNK 64                    // D_OUT / S_REL
#define TOT_E (S_REL * E_REL)       // 2,500,000
#define SEG   (S_REL * N_U)         // 500,000 segments per side
#define NBLK  ((SEG + 1023) / 1024) // 489 scan blocks

// ---------------------------------------------------------------------------
// Scratch (static bss; no allocations). Y stored fp16 (gather accumulates in
// fp32) -> halves random-gather traffic; per-relation Y slice = 12.8 MB,
// L2-resident.
// ---------------------------------------------------------------------------
__device__ __half g_Yu[(size_t)N_U * D_OUT];  // x_u @ W
__device__ __half g_Yv[(size_t)N_V * D_OUT];  // x_v @ W
__device__ int    g_off_u[SEG];               // counts -> exclusive offs -> ends
__device__ int    g_off_v[SEG];
__device__ int2   g_eu[TOT_E];                // records for zu: (col, val-bits)
__device__ int2   g_ev[TOT_E];                // records for zv: (row, val-bits)
__device__ int    g_bsum[2][512];             // scan block sums

// ---------------------------------------------------------------------------
// TF32 tensor-core GEMM: C[M, 320] = A[M, 256] @ B[256, 320], C in fp16.
// Double-buffered DYNAMIC smem, register-staged global prefetch.
// gridDim.z selects (A, C) pair so both GEMMs run in one launch.
// (Grid order identical to the proven 679.9us run.)
// ---------------------------------------------------------------------------
#define GBM 128
#define GBN 64
#define GBK 32
#define KSTEPS (D_IN / GBK)   // 8

#define AS_STRIDE (GBK + 4)                         // 36
#define BS_STRIDE (GBN + 8)                         // 72
#define AS_WORDS  (GBM * AS_STRIDE)                 // 4608 per buffer
#define BS_WORDS  (GBK * BS_STRIDE)                 // 2304 per buffer
#define GEMM_SMEM_BYTES ((2 * AS_WORDS + 2 * BS_WORDS) * 4)   // 55296

__device__ __forceinline__ uint32_t f32_to_tf32(float x)
{
    uint32_t r;
    asm("cvt.rna.tf32.f32 %0, %1;" : "=r"(r) : "f"(x));
    return r;
}

__device__ __forceinline__ void mma_tf32(float c[4],
                                         uint32_t a0, uint32_t a1,
                                         uint32_t a2, uint32_t a3,
                                         uint32_t b0, uint32_t b1)
{
    asm volatile(
        "mma.sync.aligned.m16n8k8.row.col.f32.tf32.tf32.f32 "
        "{%0,%1,%2,%3}, {%4,%5,%6,%7}, {%8,%9}, {%0,%1,%2,%3};"
        : "+f"(c[0]), "+f"(c[1]), "+f"(c[2]), "+f"(c[3])
        : "r"(a0), "r"(a1), "r"(a2), "r"(a3), "r"(b0), "r"(b1));
}

__global__ __launch_bounds__(256)
void gemm_tf32_kernel(const float* __restrict__ Au, const float* __restrict__ Av,
                      const float* __restrict__ B,
                      __half* __restrict__ Cu, __half* __restrict__ Cv, int M)
{
    extern __shared__ uint32_t dynsmem[];
    uint32_t* AsBuf[2] = { dynsmem, dynsmem + AS_WORDS };
    uint32_t* BsBuf[2] = { dynsmem + 2 * AS_WORDS,
                           dynsmem + 2 * AS_WORDS + BS_WORDS };

    const float* A = blockIdx.z ? Av : Au;
    __half*      C = blockIdx.z ? Cv : Cu;

    const int tid  = threadIdx.x;
    const int lane = tid & 31;
    const int wid  = tid >> 5;
    const int warpM = wid & 3;
    const int warpN = wid >> 2;
    const int gid = lane >> 2;
    const int tig = lane & 3;

    const int blockRow = blockIdx.x * GBM;
    const int blockCol = blockIdx.y * GBN;

    float acc[2][4][4];
#pragma unroll
    for (int mi = 0; mi < 2; mi++)
#pragma unroll
        for (int ni = 0; ni < 4; ni++)
#pragma unroll
            for (int q = 0; q < 4; q++) acc[mi][ni][q] = 0.f;

    float4 aReg[4];
    float4 bReg[2];

    auto load_tile = [&](int kb) {
#pragma unroll
        for (int it = 0; it < 4; it++) {
            int f   = tid + it * 256;
            int row = f >> 3;
            int col = (f & 7) * 4;
            int gr  = blockRow + row;
            aReg[it] = make_float4(0.f, 0.f, 0.f, 0.f);
            if (gr < M)
                aReg[it] = *reinterpret_cast<const float4*>(
                    A + (size_t)gr * D_IN + kb * GBK + col);
        }
#pragma unroll
        for (int it = 0; it < 2; it++) {
            int f   = tid + it * 256;
            int row = f >> 4;
            int col = (f & 15) * 4;
            bReg[it] = *reinterpret_cast<const float4*>(
                B + (size_t)(kb * GBK + row) * D_OUT + blockCol + col);
        }
    };

    auto store_tile = [&](int buf) {
        uint32_t* As = AsBuf[buf];
        uint32_t* Bs = BsBuf[buf];
#pragma unroll
        for (int it = 0; it < 4; it++) {
            int f   = tid + it * 256;
            int row = f >> 3;
            int col = (f & 7) * 4;
            uint4 t;
            t.x = f32_to_tf32(aReg[it].x);
            t.y = f32_to_tf32(aReg[it].y);
            t.z = f32_to_tf32(aReg[it].z);
            t.w = f32_to_tf32(aReg[it].w);
            *reinterpret_cast<uint4*>(&As[row * AS_STRIDE + col]) = t;
        }
#pragma unroll
        for (int it = 0; it < 2; it++) {
            int f   = tid + it * 256;
            int row = f >> 4;
            int col = (f & 15) * 4;
            uint4 t;
            t.x = f32_to_tf32(bReg[it].x);
            t.y = f32_to_tf32(bReg[it].y);
            t.z = f32_to_tf32(bReg[it].z);
            t.w = f32_to_tf32(bReg[it].w);
            *reinterpret_cast<uint4*>(&Bs[row * BS_STRIDE + col]) = t;
        }
    };

    auto compute_tile = [&](int buf) {
        const uint32_t* As = AsBuf[buf];
        const uint32_t* Bs = BsBuf[buf];
#pragma unroll
        for (int kk = 0; kk < GBK; kk += 8) {
            uint32_t af[2][4];
#pragma unroll
            for (int mi = 0; mi < 2; mi++) {
                int rb = warpM * 32 + mi * 16 + gid;
                af[mi][0] = As[(rb    ) * AS_STRIDE + kk + tig    ];
                af[mi][1] = As[(rb + 8) * AS_STRIDE + kk + tig    ];
                af[mi][2] = As[(rb    ) * AS_STRIDE + kk + tig + 4];
                af[mi][3] = As[(rb + 8) * AS_STRIDE + kk + tig + 4];
            }
            uint32_t bf[4][2];
#pragma unroll
            for (int ni = 0; ni < 4; ni++) {
                int cb = warpN * 32 + ni * 8 + gid;
                bf[ni][0] = Bs[(kk + tig    ) * BS_STRIDE + cb];
                bf[ni][1] = Bs[(kk + tig + 4) * BS_STRIDE + cb];
            }
#pragma unroll
            for (int mi = 0; mi < 2; mi++)
#pragma unroll
                for (int ni = 0; ni < 4; ni++)
                    mma_tf32(acc[mi][ni],
                             af[mi][0], af[mi][1], af[mi][2], af[mi][3],
                             bf[ni][0], bf[ni][1]);
        }
    };

    load_tile(0);
    store_tile(0);
    __syncthreads();

#pragma unroll
    for (int kb = 0; kb < KSTEPS; kb++) {
        if (kb + 1 < KSTEPS)
            load_tile(kb + 1);
        compute_tile(kb & 1);
        if (kb + 1 < KSTEPS) {
            store_tile((kb + 1) & 1);
            __syncthreads();
        }
    }

    // ---- epilogue: fp32 accum -> fp16 stores (2 cols per 4B) ----
#pragma unroll
    for (int mi = 0; mi < 2; mi++) {
        int r0 = blockRow + warpM * 32 + mi * 16 + gid;
#pragma unroll
        for (int ni = 0; ni < 4; ni++) {
            int cc = blockCol + warpN * 32 + ni * 8 + tig * 2;
            if (r0 < M) {
                __half2 h = __floats2half2_rn(acc[mi][ni][0], acc[mi][ni][1]);
                *reinterpret_cast<__half2*>(C + (size_t)r0 * D_OUT + cc) = h;
            }
            if (r0 + 8 < M) {
                __half2 h = __floats2half2_rn(acc[mi][ni][2], acc[mi][ni][3]);
                *reinterpret_cast<__half2*>(C + (size_t)(r0 + 8) * D_OUT + cc) = h;
            }
        }
    }
}

// ---------------------------------------------------------------------------
// CSR build step 1: histogram per (s, row) and (s, col) segment
// ---------------------------------------------------------------------------
__global__ __launch_bounds__(256)
void hist_kernel(const int* __restrict__ rows, const int* __restrict__ cols)
{
    int e = blockIdx.x * blockDim.x + threadIdx.x;
    if (e >= TOT_E) return;
    int s = e / E_REL;
    int r = __ldg(rows + e);
    int c = __ldg(cols + e);
    atomicAdd(&g_off_u[s * N_U + r], 1);
    atomicAdd(&g_off_v[s * N_V + c], 1);
}

// ---------------------------------------------------------------------------
// CSR build step 2: two-level exclusive scan over 500k counters (both sides)
// ---------------------------------------------------------------------------
__global__ __launch_bounds__(1024)
void scan1_kernel()
{
    __shared__ int sh[1024];
    int* buf = blockIdx.y ? g_off_v : g_off_u;
    int tid = threadIdx.x;
    int gid = blockIdx.x * 1024 + tid;
    int v = (gid < SEG) ? buf[gid] : 0;
    sh[tid] = v;
    __syncthreads();
#pragma unroll
    for (int d = 1; d < 1024; d <<= 1) {
        int t = (tid >= d) ? sh[tid - d] : 0;
        __syncthreads();
        sh[tid] += t;
        __syncthreads();
    }
    if (gid < SEG) buf[gid] = sh[tid] - v;     // exclusive
    if (tid == 1023) g_bsum[blockIdx.y][blockIdx.x] = sh[1023];
}

__global__ __launch_bounds__(512)
void scan2_kernel()
{
    __shared__ int sh[512];
    int tid = threadIdx.x;
    int side = blockIdx.y;
    int v = (tid < NBLK) ? g_bsum[side][tid] : 0;
    sh[tid] = v;
    __syncthreads();
#pragma unroll
    for (int d = 1; d < 512; d <<= 1) {
        int t = (tid >= d) ? sh[tid - d] : 0;
        __syncthreads();
        sh[tid] += t;
        __syncthreads();
    }
    if (tid < NBLK) g_bsum[side][tid] = sh[tid] - v;  // exclusive
}

__global__ __launch_bounds__(1024)
void scan3_kernel()
{
    int* buf = blockIdx.y ? g_off_v : g_off_u;
    int gid = blockIdx.x * 1024 + threadIdx.x;
    if (gid < SEG) buf[gid] += g_bsum[blockIdx.y][blockIdx.x];
}

// ---------------------------------------------------------------------------
// CSR build step 3: fill packed (index, val) records in segment order.
// Afterwards g_off_*[seg] holds the END of segment seg.
// ---------------------------------------------------------------------------
__global__ __launch_bounds__(256)
void fill_kernel(const float* __restrict__ vals,
                 const int*   __restrict__ rows,
                 const int*   __restrict__ cols)
{
    int e = blockIdx.x * blockDim.x + threadIdx.x;
    if (e >= TOT_E) return;
    int s = e / E_REL;
    int r = __ldg(rows + e);
    int c = __ldg(cols + e);
    int vb = __float_as_int(__ldg(vals + e));

    int pu = atomicAdd(&g_off_u[s * N_U + r], 1);
    g_eu[pu] = make_int2(c, vb);
    int pv = atomicAdd(&g_off_v[s * N_V + c], 1);
    g_ev[pv] = make_int2(r, vb);
}

// ---------------------------------------------------------------------------
// Gather: 16 threads per (s, out_row) segment, each owns 4 cols of the
// 64-wide chunk (fp16 Y -> one 8B load per edge per lane). fp32 accumulate,
// unrolled x2, write once with fused ReLU.
// ---------------------------------------------------------------------------
__device__ __forceinline__ float4 half4_to_float4(uint2 raw)
{
    __half2 h0 = *reinterpret_cast<__half2*>(&raw.x);
    __half2 h1 = *reinterpret_cast<__half2*>(&raw.y);
    float2 a = __half22float2(h0);
    float2 b = __half22float2(h1);
    return make_float4(a.x, a.y, b.x, b.y);
}

__global__ __launch_bounds__(256)
void gather_kernel(float* __restrict__ zu, float* __restrict__ zv)
{
    const int side = blockIdx.y;
    const long long t = (long long)blockIdx.x * 256 + threadIdx.x;
    const int seg  = (int)(t >> 4);
    const int lane = (int)(t & 15);
    if (seg >= SEG) return;

    const int s = seg / N_U;            // N_U == N_V
    const int orow = seg - s * N_U;
    const int off = s * CHUNK + lane * 4;

    const int2*   recs = side ? g_ev : g_eu;
    const __half* Y    = side ? g_Yu : g_Yv;
    float*        out  = side ? zv   : zu;
    const int*    ends = side ? g_off_v : g_off_u;

    const int end = __ldg(ends + seg);
    int e = seg ? __ldg(ends + seg - 1) : 0;

    float4 acc = make_float4(0.f, 0.f, 0.f, 0.f);
    for (; e + 2 <= end; e += 2) {
        int2 r0 = __ldg(recs + e);
        int2 r1 = __ldg(recs + e + 1);
        float v0 = __int_as_float(r0.y);
        float v1 = __int_as_float(r1.y);
        uint2 raw0 = *reinterpret_cast<const uint2*>(Y + (size_t)r0.x * D_OUT + off);
        uint2 raw1 = *reinterpret_cast<const uint2*>(Y + (size_t)r1.x * D_OUT + off);
        float4 y0 = half4_to_float4(raw0);
        float4 y1 = half4_to_float4(raw1);
        acc.x = fmaf(v0, y0.x, acc.x);  acc.x = fmaf(v1, y1.x, acc.x);
        acc.y = fmaf(v0, y0.y, acc.y);  acc.y = fmaf(v1, y1.y, acc.y);
        acc.z = fmaf(v0, y0.z, acc.z);  acc.z = fmaf(v1, y1.z, acc.z);
        acc.w = fmaf(v0, y0.w, acc.w);  acc.w = fmaf(v1, y1.w, acc.w);
    }
    if (e < end) {
        int2 rec = __ldg(recs + e);
        float val = __int_as_float(rec.y);
        uint2 raw = *reinterpret_cast<const uint2*>(Y + (size_t)rec.x * D_OUT + off);
        float4 y = half4_to_float4(raw);
        acc.x = fmaf(val, y.x, acc.x);
        acc.y = fmaf(val, y.y, acc.y);
        acc.z = fmaf(val, y.z, acc.z);
        acc.w = fmaf(val, y.w, acc.w);
    }
    acc.x = fmaxf(acc.x, 0.f);
    acc.y = fmaxf(acc.y, 0.f);
    acc.z = fmaxf(acc.z, 0.f);
    acc.w = fmaxf(acc.w, 0.f);
    *reinterpret_cast<float4*>(out + (size_t)orow * D_OUT + off) = acc;
}

// ---------------------------------------------------------------------------
// Launch: GEMMs on the main stream, CSR build concurrently on a side stream
// (event fork/join — identical structure to the proven 679.9us run).
// ---------------------------------------------------------------------------
extern "C" void kernel_launch(void* const* d_in, const int* in_sizes, int n_in,
                              void* d_out, int out_size)
{
    const float* x_u      = (const float*)d_in[0];  // [N_U, D_IN]
    const float* x_v      = (const float*)d_in[1];  // [N_V, D_IN]
    const float* W        = (const float*)d_in[2];  // [D_IN, D_OUT]
    const float* sup_vals = (const float*)d_in[3];  // [S, E]
    const int*   sup_rows = (const int*)  d_in[4];  // [S, E]
    const int*   sup_cols = (const int*)  d_in[5];  // [S, E]

    float* zu = (float*)d_out;                       // [N_U, D_OUT]
    float* zv = zu + (size_t)N_U * D_OUT;            // [N_V, D_OUT]

    __half* dYu = nullptr;
    __half* dYv = nullptr;
    void*   dOffU = nullptr;
    void*   dOffV = nullptr;
    cudaGetSymbolAddress((void**)&dYu, g_Yu);
    cudaGetSymbolAddress((void**)&dYv, g_Yv);
    cudaGetSymbolAddress(&dOffU, g_off_u);
    cudaGetSymbolAddress(&dOffV, g_off_v);

    cudaFuncSetAttribute(gemm_tf32_kernel,
                         cudaFuncAttributeMaxDynamicSharedMemorySize,
                         GEMM_SMEM_BYTES);

    cudaStream_t s2;
    cudaEvent_t evFork, evJoin;
    cudaStreamCreateWithFlags(&s2, cudaStreamNonBlocking);
    cudaEventCreateWithFlags(&evFork, cudaEventDisableTiming);
    cudaEventCreateWithFlags(&evJoin, cudaEventDisableTiming);

    cudaEventRecord(evFork, 0);
    cudaStreamWaitEvent(s2, evFork, 0);

    // --- main stream: both GEMMs in one launch (tensor pipe) ---
    {
        dim3 grid((N_U + GBM - 1) / GBM, D_OUT / GBN, 2);
        gemm_tf32_kernel<<<grid, 256, GEMM_SMEM_BYTES>>>(x_u, x_v, W, dYu, dYv, N_U);
    }

    // --- side stream: CSR build (LSU / L2-atomic pipe) ---
    cudaMemsetAsync(dOffU, 0, SEG * sizeof(int), s2);
    cudaMemsetAsync(dOffV, 0, SEG * sizeof(int), s2);
    {
        int threads = 256;
        int blocks = (TOT_E + threads - 1) / threads;
        hist_kernel<<<blocks, threads, 0, s2>>>(sup_rows, sup_cols);
        dim3 g1(NBLK, 2);
        scan1_kernel<<<g1, 1024, 0, s2>>>();
        dim3 g2(1, 2);
        scan2_kernel<<<g2, 512, 0, s2>>>();
        dim3 g3(NBLK, 2);
        scan3_kernel<<<g3, 1024, 0, s2>>>();
        fill_kernel<<<blocks, threads, 0, s2>>>(sup_vals, sup_rows, sup_cols);
    }

    cudaEventRecord(evJoin, s2);
    cudaStreamWaitEvent(0, evJoin, 0);

    // --- gather with fused ReLU ---
    {
        long long total = (long long)SEG * 16;
        dim3 grid((unsigned)((total + 255) / 256), 2);
        gather_kernel<<<grid, 256>>>(zu, zv);
    }
}

// round 12
// speedup vs baseline: 2.0921x; 1.0035x over previous
#include <cuda_runtime.h>
#include <cuda_fp16.h>
#include <cstdint>

// Problem constants (match reference)
#define N_U   100000
#define N_V   100000
#define D_IN  256
#define D_OUT 320
#define S_REL 5
#define E_REL 500000
#define CHUNK 64                    // D_OUT / S_REL
#define TOT_E (S_REL * E_REL)       // 2,500,000
#define SEG   (S_REL * N_U)         // 500,000 segments per side
#define NBLK  ((SEG + 1023) / 1024) // 489 scan blocks

// ---------------------------------------------------------------------------
// Scratch (static bss; no allocations). Y stored fp16 (gather accumulates in
// fp32) -> halves random-gather traffic; per-relation Y slice = 12.8 MB,
// L2-resident.
// ---------------------------------------------------------------------------
__device__ __half g_Yu[(size_t)N_U * D_OUT];  // x_u @ W
__device__ __half g_Yv[(size_t)N_V * D_OUT];  // x_v @ W
__device__ int    g_off_u[SEG];               // counts -> exclusive offs -> ends
__device__ int    g_off_v[SEG];
__device__ int2   g_eu[TOT_E];                // records for zu: (col, val-bits)
__device__ int2   g_ev[TOT_E];                // records for zv: (row, val-bits)
__device__ int    g_bsum[2][512];             // scan block sums

// ---------------------------------------------------------------------------
// TF32 tensor-core GEMM: C[M, 320] = A[M, 256] @ B[256, 320], C in fp16.
// Double-buffered dynamic smem, register-staged global prefetch.
// blockIdx.x = N-tile (fastest) so the 5 blocks sharing an A-tile are
// launch-adjacent -> A DRAM-read once, L2-served for the other 4 N-tiles.
// blockIdx.z selects the (A, C) pair so both GEMMs run in one launch.
// ---------------------------------------------------------------------------
#define GBM 128
#define GBN 64
#define GBK 32
#define KSTEPS (D_IN / GBK)   // 8

#define AS_STRIDE (GBK + 4)                         // 36
#define BS_STRIDE (GBN + 8)                         // 72
#define AS_WORDS  (GBM * AS_STRIDE)                 // 4608 per buffer
#define BS_WORDS  (GBK * BS_STRIDE)                 // 2304 per buffer
#define GEMM_SMEM_BYTES ((2 * AS_WORDS + 2 * BS_WORDS) * 4)   // 55296

__device__ __forceinline__ uint32_t f32_to_tf32(float x)
{
    uint32_t r;
    asm("cvt.rna.tf32.f32 %0, %1;" : "=r"(r) : "f"(x));
    return r;
}

__device__ __forceinline__ void mma_tf32(float c[4],
                                         uint32_t a0, uint32_t a1,
                                         uint32_t a2, uint32_t a3,
                                         uint32_t b0, uint32_t b1)
{
    asm volatile(
        "mma.sync.aligned.m16n8k8.row.col.f32.tf32.tf32.f32 "
        "{%0,%1,%2,%3}, {%4,%5,%6,%7}, {%8,%9}, {%0,%1,%2,%3};"
        : "+f"(c[0]), "+f"(c[1]), "+f"(c[2]), "+f"(c[3])
        : "r"(a0), "r"(a1), "r"(a2), "r"(a3), "r"(b0), "r"(b1));
}

__global__ __launch_bounds__(256)
void gemm_tf32_kernel(const float* __restrict__ Au, const float* __restrict__ Av,
                      const float* __restrict__ B,
                      __half* __restrict__ Cu, __half* __restrict__ Cv, int M)
{
    extern __shared__ uint32_t dynsmem[];
    uint32_t* AsBuf[2] = { dynsmem, dynsmem + AS_WORDS };
    uint32_t* BsBuf[2] = { dynsmem + 2 * AS_WORDS,
                           dynsmem + 2 * AS_WORDS + BS_WORDS };

    const float* A = blockIdx.z ? Av : Au;
    __half*      C = blockIdx.z ? Cv : Cu;

    const int tid  = threadIdx.x;
    const int lane = tid & 31;
    const int wid  = tid >> 5;
    const int warpM = wid & 3;
    const int warpN = wid >> 2;
    const int gid = lane >> 2;
    const int tig = lane & 3;

    const int blockRow = blockIdx.y * GBM;   // M tile (slow dim)
    const int blockCol = blockIdx.x * GBN;   // N tile (fast dim -> A L2 reuse)

    float acc[2][4][4];
#pragma unroll
    for (int mi = 0; mi < 2; mi++)
#pragma unroll
        for (int ni = 0; ni < 4; ni++)
#pragma unroll
            for (int q = 0; q < 4; q++) acc[mi][ni][q] = 0.f;

    float4 aReg[4];
    float4 bReg[2];

    auto load_tile = [&](int kb) {
#pragma unroll
        for (int it = 0; it < 4; it++) {
            int f   = tid + it * 256;
            int row = f >> 3;
            int col = (f & 7) * 4;
            int gr  = blockRow + row;
            aReg[it] = make_float4(0.f, 0.f, 0.f, 0.f);
            if (gr < M)
                aReg[it] = *reinterpret_cast<const float4*>(
                    A + (size_t)gr * D_IN + kb * GBK + col);
        }
#pragma unroll
        for (int it = 0; it < 2; it++) {
            int f   = tid + it * 256;
            int row = f >> 4;
            int col = (f & 15) * 4;
            bReg[it] = *reinterpret_cast<const float4*>(
                B + (size_t)(kb * GBK + row) * D_OUT + blockCol + col);
        }
    };

    auto store_tile = [&](int buf) {
        uint32_t* As = AsBuf[buf];
        uint32_t* Bs = BsBuf[buf];
#pragma unroll
        for (int it = 0; it < 4; it++) {
            int f   = tid + it * 256;
            int row = f >> 3;
            int col = (f & 7) * 4;
            uint4 t;
            t.x = f32_to_tf32(aReg[it].x);
            t.y = f32_to_tf32(aReg[it].y);
            t.z = f32_to_tf32(aReg[it].z);
            t.w = f32_to_tf32(aReg[it].w);
            *reinterpret_cast<uint4*>(&As[row * AS_STRIDE + col]) = t;
        }
#pragma unroll
        for (int it = 0; it < 2; it++) {
            int f   = tid + it * 256;
            int row = f >> 4;
            int col = (f & 15) * 4;
            uint4 t;
            t.x = f32_to_tf32(bReg[it].x);
            t.y = f32_to_tf32(bReg[it].y);
            t.z = f32_to_tf32(bReg[it].z);
            t.w = f32_to_tf32(bReg[it].w);
            *reinterpret_cast<uint4*>(&Bs[row * BS_STRIDE + col]) = t;
        }
    };

    auto compute_tile = [&](int buf) {
        const uint32_t* As = AsBuf[buf];
        const uint32_t* Bs = BsBuf[buf];
#pragma unroll
        for (int kk = 0; kk < GBK; kk += 8) {
            uint32_t af[2][4];
#pragma unroll
            for (int mi = 0; mi < 2; mi++) {
                int rb = warpM * 32 + mi * 16 + gid;
                af[mi][0] = As[(rb    ) * AS_STRIDE + kk + tig    ];
                af[mi][1] = As[(rb + 8) * AS_STRIDE + kk + tig    ];
                af[mi][2] = As[(rb    ) * AS_STRIDE + kk + tig + 4];
                af[mi][3] = As[(rb + 8) * AS_STRIDE + kk + tig + 4];
            }
            uint32_t bf[4][2];
#pragma unroll
            for (int ni = 0; ni < 4; ni++) {
                int cb = warpN * 32 + ni * 8 + gid;
                bf[ni][0] = Bs[(kk + tig    ) * BS_STRIDE + cb];
                bf[ni][1] = Bs[(kk + tig + 4) * BS_STRIDE + cb];
            }
#pragma unroll
            for (int mi = 0; mi < 2; mi++)
#pragma unroll
                for (int ni = 0; ni < 4; ni++)
                    mma_tf32(acc[mi][ni],
                             af[mi][0], af[mi][1], af[mi][2], af[mi][3],
                             bf[ni][0], bf[ni][1]);
        }
    };

    load_tile(0);
    store_tile(0);
    __syncthreads();

#pragma unroll
    for (int kb = 0; kb < KSTEPS; kb++) {
        if (kb + 1 < KSTEPS)
            load_tile(kb + 1);
        compute_tile(kb & 1);
        if (kb + 1 < KSTEPS) {
            store_tile((kb + 1) & 1);
            __syncthreads();
        }
    }

    // ---- epilogue: fp32 accum -> fp16 stores (2 cols per 4B) ----
#pragma unroll
    for (int mi = 0; mi < 2; mi++) {
        int r0 = blockRow + warpM * 32 + mi * 16 + gid;
#pragma unroll
        for (int ni = 0; ni < 4; ni++) {
            int cc = blockCol + warpN * 32 + ni * 8 + tig * 2;
            if (r0 < M) {
                __half2 h = __floats2half2_rn(acc[mi][ni][0], acc[mi][ni][1]);
                *reinterpret_cast<__half2*>(C + (size_t)r0 * D_OUT + cc) = h;
            }
            if (r0 + 8 < M) {
                __half2 h = __floats2half2_rn(acc[mi][ni][2], acc[mi][ni][3]);
                *reinterpret_cast<__half2*>(C + (size_t)(r0 + 8) * D_OUT + cc) = h;
            }
        }
    }
}

// ---------------------------------------------------------------------------
// CSR build step 1: histogram per (s, row) and (s, col) segment
// ---------------------------------------------------------------------------
__global__ __launch_bounds__(256)
void hist_kernel(const int* __restrict__ rows, const int* __restrict__ cols)
{
    int e = blockIdx.x * blockDim.x + threadIdx.x;
    if (e >= TOT_E) return;
    int s = e / E_REL;
    int r = __ldg(rows + e);
    int c = __ldg(cols + e);
    atomicAdd(&g_off_u[s * N_U + r], 1);
    atomicAdd(&g_off_v[s * N_V + c], 1);
}

// ---------------------------------------------------------------------------
// CSR build step 2: two-level exclusive scan over 500k counters (both sides)
// ---------------------------------------------------------------------------
__global__ __launch_bounds__(1024)
void scan1_kernel()
{
    __shared__ int sh[1024];
    int* buf = blockIdx.y ? g_off_v : g_off_u;
    int tid = threadIdx.x;
    int gid = blockIdx.x * 1024 + tid;
    int v = (gid < SEG) ? buf[gid] : 0;
    sh[tid] = v;
    __syncthreads();
#pragma unroll
    for (int d = 1; d < 1024; d <<= 1) {
        int t = (tid >= d) ? sh[tid - d] : 0;
        __syncthreads();
        sh[tid] += t;
        __syncthreads();
    }
    if (gid < SEG) buf[gid] = sh[tid] - v;     // exclusive
    if (tid == 1023) g_bsum[blockIdx.y][blockIdx.x] = sh[1023];
}

__global__ __launch_bounds__(512)
void scan2_kernel()
{
    __shared__ int sh[512];
    int tid = threadIdx.x;
    int side = blockIdx.y;
    int v = (tid < NBLK) ? g_bsum[side][tid] : 0;
    sh[tid] = v;
    __syncthreads();
#pragma unroll
    for (int d = 1; d < 512; d <<= 1) {
        int t = (tid >= d) ? sh[tid - d] : 0;
        __syncthreads();
        sh[tid] += t;
        __syncthreads();
    }
    if (tid < NBLK) g_bsum[side][tid] = sh[tid] - v;  // exclusive
}

__global__ __launch_bounds__(1024)
void scan3_kernel()
{
    int* buf = blockIdx.y ? g_off_v : g_off_u;
    int gid = blockIdx.x * 1024 + threadIdx.x;
    if (gid < SEG) buf[gid] += g_bsum[blockIdx.y][blockIdx.x];
}

// ---------------------------------------------------------------------------
// CSR build step 3: fill packed (index, val) records in segment order.
// Afterwards g_off_*[seg] holds the END of segment seg.
// ---------------------------------------------------------------------------
__global__ __launch_bounds__(256)
void fill_kernel(const float* __restrict__ vals,
                 const int*   __restrict__ rows,
                 const int*   __restrict__ cols)
{
    int e = blockIdx.x * blockDim.x + threadIdx.x;
    if (e >= TOT_E) return;
    int s = e / E_REL;
    int r = __ldg(rows + e);
    int c = __ldg(cols + e);
    int vb = __float_as_int(__ldg(vals + e));

    int pu = atomicAdd(&g_off_u[s * N_U + r], 1);
    g_eu[pu] = make_int2(c, vb);
    int pv = atomicAdd(&g_off_v[s * N_V + c], 1);
    g_ev[pv] = make_int2(r, vb);
}

// ---------------------------------------------------------------------------
// Gather: 8 threads per (s, out_row) segment, each owns 8 cols of the
// 64-wide chunk (fp16 -> one 16B load per edge per lane; half the LDG issue
// count vs 16x8B). fp32 accumulate, unrolled x2, fused ReLU, write once.
// ---------------------------------------------------------------------------
__device__ __forceinline__ void half8_fma(float4& a0, float4& a1,
                                          uint4 raw, float v)
{
    float2 f0 = __half22float2(*reinterpret_cast<__half2*>(&raw.x));
    float2 f1 = __half22float2(*reinterpret_cast<__half2*>(&raw.y));
    float2 f2 = __half22float2(*reinterpret_cast<__half2*>(&raw.z));
    float2 f3 = __half22float2(*reinterpret_cast<__half2*>(&raw.w));
    a0.x = fmaf(v, f0.x, a0.x);  a0.y = fmaf(v, f0.y, a0.y);
    a0.z = fmaf(v, f1.x, a0.z);  a0.w = fmaf(v, f1.y, a0.w);
    a1.x = fmaf(v, f2.x, a1.x);  a1.y = fmaf(v, f2.y, a1.y);
    a1.z = fmaf(v, f3.x, a1.z);  a1.w = fmaf(v, f3.y, a1.w);
}

__global__ __launch_bounds__(256)
void gather_kernel(float* __restrict__ zu, float* __restrict__ zv)
{
    const int side = blockIdx.y;
    const long long t = (long long)blockIdx.x * 256 + threadIdx.x;
    const int seg  = (int)(t >> 3);
    const int lane = (int)(t & 7);
    if (seg >= SEG) return;

    const int s = seg / N_U;            // N_U == N_V
    const int orow = seg - s * N_U;
    const int off = s * CHUNK + lane * 8;

    const int2*   recs = side ? g_ev : g_eu;
    const __half* Y    = side ? g_Yu : g_Yv;
    float*        out  = side ? zv   : zu;
    const int*    ends = side ? g_off_v : g_off_u;

    const int end = __ldg(ends + seg);
    int e = seg ? __ldg(ends + seg - 1) : 0;

    float4 acc0 = make_float4(0.f, 0.f, 0.f, 0.f);
    float4 acc1 = make_float4(0.f, 0.f, 0.f, 0.f);
    for (; e + 2 <= end; e += 2) {
        int2 r0 = __ldg(recs + e);
        int2 r1 = __ldg(recs + e + 1);
        uint4 raw0 = *reinterpret_cast<const uint4*>(Y + (size_t)r0.x * D_OUT + off);
        uint4 raw1 = *reinterpret_cast<const uint4*>(Y + (size_t)r1.x * D_OUT + off);
        half8_fma(acc0, acc1, raw0, __int_as_float(r0.y));
        half8_fma(acc0, acc1, raw1, __int_as_float(r1.y));
    }
    if (e < end) {
        int2 rec = __ldg(recs + e);
        uint4 raw = *reinterpret_cast<const uint4*>(Y + (size_t)rec.x * D_OUT + off);
        half8_fma(acc0, acc1, raw, __int_as_float(rec.y));
    }
    acc0.x = fmaxf(acc0.x, 0.f);  acc0.y = fmaxf(acc0.y, 0.f);
    acc0.z = fmaxf(acc0.z, 0.f);  acc0.w = fmaxf(acc0.w, 0.f);
    acc1.x = fmaxf(acc1.x, 0.f);  acc1.y = fmaxf(acc1.y, 0.f);
    acc1.z = fmaxf(acc1.z, 0.f);  acc1.w = fmaxf(acc1.w, 0.f);
    float* dst = out + (size_t)orow * D_OUT + off;
    *reinterpret_cast<float4*>(dst)     = acc0;
    *reinterpret_cast<float4*>(dst + 4) = acc1;
}

// ---------------------------------------------------------------------------
// Launch: GEMMs on the main stream, CSR build concurrently on a side stream
// (event fork/join — graph-capture legal), gather after the join.
// ---------------------------------------------------------------------------
extern "C" void kernel_launch(void* const* d_in, const int* in_sizes, int n_in,
                              void* d_out, int out_size)
{
    const float* x_u      = (const float*)d_in[0];  // [N_U, D_IN]
    const float* x_v      = (const float*)d_in[1];  // [N_V, D_IN]
    const float* W        = (const float*)d_in[2];  // [D_IN, D_OUT]
    const float* sup_vals = (const float*)d_in[3];  // [S, E]
    const int*   sup_rows = (const int*)  d_in[4];  // [S, E]
    const int*   sup_cols = (const int*)  d_in[5];  // [S, E]

    float* zu = (float*)d_out;                       // [N_U, D_OUT]
    float* zv = zu + (size_t)N_U * D_OUT;            // [N_V, D_OUT]

    __half* dYu = nullptr;
    __half* dYv = nullptr;
    void*   dOffU = nullptr;
    void*   dOffV = nullptr;
    cudaGetSymbolAddress((void**)&dYu, g_Yu);
    cudaGetSymbolAddress((void**)&dYv, g_Yv);
    cudaGetSymbolAddress(&dOffU, g_off_u);
    cudaGetSymbolAddress(&dOffV, g_off_v);

    cudaFuncSetAttribute(gemm_tf32_kernel,
                         cudaFuncAttributeMaxDynamicSharedMemorySize,
                         GEMM_SMEM_BYTES);

    cudaStream_t s2;
    cudaEvent_t evFork, evJoin;
    cudaStreamCreateWithFlags(&s2, cudaStreamNonBlocking);
    cudaEventCreateWithFlags(&evFork, cudaEventDisableTiming);
    cudaEventCreateWithFlags(&evJoin, cudaEventDisableTiming);

    cudaEventRecord(evFork, 0);
    cudaStreamWaitEvent(s2, evFork, 0);

    // --- main stream: both GEMMs in one launch (tensor pipe) ---
    {
        dim3 grid(D_OUT / GBN, (N_U + GBM - 1) / GBM, 2);   // x = N tile (fast)
        gemm_tf32_kernel<<<grid, 256, GEMM_SMEM_BYTES>>>(x_u, x_v, W, dYu, dYv, N_U);
    }

    // --- side stream: CSR build (LSU / L2-atomic pipe) ---
    cudaMemsetAsync(dOffU, 0, SEG * sizeof(int), s2);
    cudaMemsetAsync(dOffV, 0, SEG * sizeof(int), s2);
    {
        int threads = 256;
        int blocks = (TOT_E + threads - 1) / threads;
        hist_kernel<<<blocks, threads, 0, s2>>>(sup_rows, sup_cols);
        dim3 g1(NBLK, 2);
        scan1_kernel<<<g1, 1024, 0, s2>>>();
        dim3 g2(1, 2);
        scan2_kernel<<<g2, 512, 0, s2>>>();
        dim3 g3(NBLK, 2);
        scan3_kernel<<<g3, 1024, 0, s2>>>();
        fill_kernel<<<blocks, threads, 0, s2>>>(sup_vals, sup_rows, sup_cols);
    }

    cudaEventRecord(evJoin, s2);
    cudaStreamWaitEvent(0, evJoin, 0);

    // --- gather with fused ReLU ---
    {
        long long total = (long long)SEG * 8;
        dim3 grid((unsigned)((total + 255) / 256), 2);
        gather_kernel<<<grid, 256>>>(zu, zv);
    }
}

// round 14
// speedup vs baseline: 2.2061x; 1.0545x over previous
#include <cuda_runtime.h>
#include <cuda_fp16.h>
#include <cstdint>

// Problem constants (match reference)
#define N_U   100000
#define N_V   100000
#define D_IN  256
#define D_OUT 320
#define S_REL 5
#define E_REL 500000
#define CHUNK 64                    // D_OUT / S_REL
#define TOT_E (S_REL * E_REL)       // 2,500,000
#define SEG   (S_REL * N_U)         // 500,000 segments per side
#define NBLK  ((SEG + 1023) / 1024) // 489 scan blocks

// ---------------------------------------------------------------------------
// Scratch (static bss; no allocations). Y stored fp16 (gather accumulates in
// fp32) -> halves random-gather traffic; per-relation Y slice = 12.8 MB,
// L2-resident.
// ---------------------------------------------------------------------------
__device__ __half g_Yu[(size_t)N_U * D_OUT];  // x_u @ W
__device__ __half g_Yv[(size_t)N_V * D_OUT];  // x_v @ W
__device__ int    g_off_u[SEG];               // counts -> exclusive offs -> ends
__device__ int    g_off_v[SEG];
__device__ int2   g_eu[TOT_E];                // records for zu: (col, val-bits)
__device__ int2   g_ev[TOT_E];                // records for zv: (row, val-bits)
__device__ int    g_bsum[2][512];             // scan block sums

// ---------------------------------------------------------------------------
// TF32 tensor-core GEMM: C[M, 320] = A[M, 256] @ B[256, 320], C in fp16.
// Double-buffered dynamic smem, register-staged global prefetch.
// blockIdx.x = N-tile (fastest); blockIdx.z selects the (A, C) pair.
// ---------------------------------------------------------------------------
#define GBM 128
#define GBN 64
#define GBK 32
#define KSTEPS (D_IN / GBK)   // 8

#define AS_STRIDE (GBK + 4)                         // 36
#define BS_STRIDE (GBN + 8)                         // 72
#define AS_WORDS  (GBM * AS_STRIDE)                 // 4608 per buffer
#define BS_WORDS  (GBK * BS_STRIDE)                 // 2304 per buffer
#define GEMM_SMEM_BYTES ((2 * AS_WORDS + 2 * BS_WORDS) * 4)   // 55296

__device__ __forceinline__ uint32_t f32_to_tf32(float x)
{
    uint32_t r;
    asm("cvt.rna.tf32.f32 %0, %1;" : "=r"(r) : "f"(x));
    return r;
}

__device__ __forceinline__ void mma_tf32(float c[4],
                                         uint32_t a0, uint32_t a1,
                                         uint32_t a2, uint32_t a3,
                                         uint32_t b0, uint32_t b1)
{
    asm volatile(
        "mma.sync.aligned.m16n8k8.row.col.f32.tf32.tf32.f32 "
        "{%0,%1,%2,%3}, {%4,%5,%6,%7}, {%8,%9}, {%0,%1,%2,%3};"
        : "+f"(c[0]), "+f"(c[1]), "+f"(c[2]), "+f"(c[3])
        : "r"(a0), "r"(a1), "r"(a2), "r"(a3), "r"(b0), "r"(b1));
}

__global__ __launch_bounds__(256)
void gemm_tf32_kernel(const float* __restrict__ Au, const float* __restrict__ Av,
                      const float* __restrict__ B,
                      __half* __restrict__ Cu, __half* __restrict__ Cv, int M)
{
    extern __shared__ uint32_t dynsmem[];
    uint32_t* AsBuf[2] = { dynsmem, dynsmem + AS_WORDS };
    uint32_t* BsBuf[2] = { dynsmem + 2 * AS_WORDS,
                           dynsmem + 2 * AS_WORDS + BS_WORDS };

    const float* A = blockIdx.z ? Av : Au;
    __half*      C = blockIdx.z ? Cv : Cu;

    const int tid  = threadIdx.x;
    const int lane = tid & 31;
    const int wid  = tid >> 5;
    const int warpM = wid & 3;
    const int warpN = wid >> 2;
    const int gid = lane >> 2;
    const int tig = lane & 3;

    const int blockRow = blockIdx.y * GBM;   // M tile (slow dim)
    const int blockCol = blockIdx.x * GBN;   // N tile (fast dim -> A L2 reuse)

    float acc[2][4][4];
#pragma unroll
    for (int mi = 0; mi < 2; mi++)
#pragma unroll
        for (int ni = 0; ni < 4; ni++)
#pragma unroll
            for (int q = 0; q < 4; q++) acc[mi][ni][q] = 0.f;

    float4 aReg[4];
    float4 bReg[2];

    auto load_tile = [&](int kb) {
#pragma unroll
        for (int it = 0; it < 4; it++) {
            int f   = tid + it * 256;
            int row = f >> 3;
            int col = (f & 7) * 4;
            int gr  = blockRow + row;
            aReg[it] = make_float4(0.f, 0.f, 0.f, 0.f);
            if (gr < M)
                aReg[it] = *reinterpret_cast<const float4*>(
                    A + (size_t)gr * D_IN + kb * GBK + col);
        }
#pragma unroll
        for (int it = 0; it < 2; it++) {
            int f   = tid + it * 256;
            int row = f >> 4;
            int col = (f & 15) * 4;
            bReg[it] = *reinterpret_cast<const float4*>(
                B + (size_t)(kb * GBK + row) * D_OUT + blockCol + col);
        }
    };

    auto store_tile = [&](int buf) {
        uint32_t* As = AsBuf[buf];
        uint32_t* Bs = BsBuf[buf];
#pragma unroll
        for (int it = 0; it < 4; it++) {
            int f   = tid + it * 256;
            int row = f >> 3;
            int col = (f & 7) * 4;
            uint4 t;
            t.x = f32_to_tf32(aReg[it].x);
            t.y = f32_to_tf32(aReg[it].y);
            t.z = f32_to_tf32(aReg[it].z);
            t.w = f32_to_tf32(aReg[it].w);
            *reinterpret_cast<uint4*>(&As[row * AS_STRIDE + col]) = t;
        }
#pragma unroll
        for (int it = 0; it < 2; it++) {
            int f   = tid + it * 256;
            int row = f >> 4;
            int col = (f & 15) * 4;
            uint4 t;
            t.x = f32_to_tf32(bReg[it].x);
            t.y = f32_to_tf32(bReg[it].y);
            t.z = f32_to_tf32(bReg[it].z);
            t.w = f32_to_tf32(bReg[it].w);
            *reinterpret_cast<uint4*>(&Bs[row * BS_STRIDE + col]) = t;
        }
    };

    auto compute_tile = [&](int buf) {
        const uint32_t* As = AsBuf[buf];
        const uint32_t* Bs = BsBuf[buf];
#pragma unroll
        for (int kk = 0; kk < GBK; kk += 8) {
            uint32_t af[2][4];
#pragma unroll
            for (int mi = 0; mi < 2; mi++) {
                int rb = warpM * 32 + mi * 16 + gid;
                af[mi][0] = As[(rb    ) * AS_STRIDE + kk + tig    ];
                af[mi][1] = As[(rb + 8) * AS_STRIDE + kk + tig    ];
                af[mi][2] = As[(rb    ) * AS_STRIDE + kk + tig + 4];
                af[mi][3] = As[(rb + 8) * AS_STRIDE + kk + tig + 4];
            }
            uint32_t bf[4][2];
#pragma unroll
            for (int ni = 0; ni < 4; ni++) {
                int cb = warpN * 32 + ni * 8 + gid;
                bf[ni][0] = Bs[(kk + tig    ) * BS_STRIDE + cb];
                bf[ni][1] = Bs[(kk + tig + 4) * BS_STRIDE + cb];
            }
#pragma unroll
            for (int mi = 0; mi < 2; mi++)
#pragma unroll
                for (int ni = 0; ni < 4; ni++)
                    mma_tf32(acc[mi][ni],
                             af[mi][0], af[mi][1], af[mi][2], af[mi][3],
                             bf[ni][0], bf[ni][1]);
        }
    };

    load_tile(0);
    store_tile(0);
    __syncthreads();

#pragma unroll
    for (int kb = 0; kb < KSTEPS; kb++) {
        if (kb + 1 < KSTEPS)
            load_tile(kb + 1);
        compute_tile(kb & 1);
        if (kb + 1 < KSTEPS) {
            store_tile((kb + 1) & 1);
            __syncthreads();
        }
    }

    // ---- epilogue: fp32 accum -> fp16 stores (2 cols per 4B) ----
#pragma unroll
    for (int mi = 0; mi < 2; mi++) {
        int r0 = blockRow + warpM * 32 + mi * 16 + gid;
#pragma unroll
        for (int ni = 0; ni < 4; ni++) {
            int cc = blockCol + warpN * 32 + ni * 8 + tig * 2;
            if (r0 < M) {
                __half2 h = __floats2half2_rn(acc[mi][ni][0], acc[mi][ni][1]);
                *reinterpret_cast<__half2*>(C + (size_t)r0 * D_OUT + cc) = h;
            }
            if (r0 + 8 < M) {
                __half2 h = __floats2half2_rn(acc[mi][ni][2], acc[mi][ni][3]);
                *reinterpret_cast<__half2*>(C + (size_t)(r0 + 8) * D_OUT + cc) = h;
            }
        }
    }
}

// ---------------------------------------------------------------------------
// CSR build step 1: histogram; 2 edges per thread (E_REL even -> a pair never
// straddles a relation boundary; 8B-aligned vector loads).
// ---------------------------------------------------------------------------
__global__ __launch_bounds__(256)
void hist_kernel(const int* __restrict__ rows, const int* __restrict__ cols)
{
    int e = (blockIdx.x * blockDim.x + threadIdx.x) * 2;
    if (e >= TOT_E) return;
    int s = e / E_REL;
    int2 r2 = *reinterpret_cast<const int2*>(rows + e);
    int2 c2 = *reinterpret_cast<const int2*>(cols + e);
    atomicAdd(&g_off_u[s * N_U + r2.x], 1);
    atomicAdd(&g_off_u[s * N_U + r2.y], 1);
    atomicAdd(&g_off_v[s * N_V + c2.x], 1);
    atomicAdd(&g_off_v[s * N_V + c2.y], 1);
}

// ---------------------------------------------------------------------------
// CSR build step 2: two-level exclusive scan over 500k counters (both sides)
// ---------------------------------------------------------------------------
__global__ __launch_bounds__(1024)
void scan1_kernel()
{
    __shared__ int sh[1024];
    int* buf = blockIdx.y ? g_off_v : g_off_u;
    int tid = threadIdx.x;
    int gid = blockIdx.x * 1024 + tid;
    int v = (gid < SEG) ? buf[gid] : 0;
    sh[tid] = v;
    __syncthreads();
#pragma unroll
    for (int d = 1; d < 1024; d <<= 1) {
        int t = (tid >= d) ? sh[tid - d] : 0;
        __syncthreads();
        sh[tid] += t;
        __syncthreads();
    }
    if (gid < SEG) buf[gid] = sh[tid] - v;     // exclusive
    if (tid == 1023) g_bsum[blockIdx.y][blockIdx.x] = sh[1023];
}

__global__ __launch_bounds__(512)
void scan2_kernel()
{
    __shared__ int sh[512];
    int tid = threadIdx.x;
    int side = blockIdx.y;
    int v = (tid < NBLK) ? g_bsum[side][tid] : 0;
    sh[tid] = v;
    __syncthreads();
#pragma unroll
    for (int d = 1; d < 512; d <<= 1) {
        int t = (tid >= d) ? sh[tid - d] : 0;
        __syncthreads();
        sh[tid] += t;
        __syncthreads();
    }
    if (tid < NBLK) g_bsum[side][tid] = sh[tid] - v;  // exclusive
}

__global__ __launch_bounds__(1024)
void scan3_kernel()
{
    int* buf = blockIdx.y ? g_off_v : g_off_u;
    int gid = blockIdx.x * 1024 + threadIdx.x;
    if (gid < SEG) buf[gid] += g_bsum[blockIdx.y][blockIdx.x];
}

// ---------------------------------------------------------------------------
// CSR build step 3: fill records; 2 edges per thread.
// Afterwards g_off_*[seg] holds the END of segment seg.
// ---------------------------------------------------------------------------
__global__ __launch_bounds__(256)
void fill_kernel(const float* __restrict__ vals,
                 const int*   __restrict__ rows,
                 const int*   __restrict__ cols)
{
    int e = (blockIdx.x * blockDim.x + threadIdx.x) * 2;
    if (e >= TOT_E) return;
    int s = e / E_REL;
    int2   r2 = *reinterpret_cast<const int2*>(rows + e);
    int2   c2 = *reinterpret_cast<const int2*>(cols + e);
    float2 v2 = *reinterpret_cast<const float2*>(vals + e);

    int pu0 = atomicAdd(&g_off_u[s * N_U + r2.x], 1);
    g_eu[pu0] = make_int2(c2.x, __float_as_int(v2.x));
    int pu1 = atomicAdd(&g_off_u[s * N_U + r2.y], 1);
    g_eu[pu1] = make_int2(c2.y, __float_as_int(v2.y));

    int pv0 = atomicAdd(&g_off_v[s * N_V + c2.x], 1);
    g_ev[pv0] = make_int2(r2.x, __float_as_int(v2.x));
    int pv1 = atomicAdd(&g_off_v[s * N_V + c2.y], 1);
    g_ev[pv1] = make_int2(r2.y, __float_as_int(v2.y));
}

// ---------------------------------------------------------------------------
// Gather: 8 threads per (s, out_row) segment, each owns 8 cols of the
// 64-wide chunk (one 16B load per edge per lane; the 8 lanes of a segment
// cover a coalesced 128B row read per edge). fp32 accumulate, unrolled x4
// for MLP, fused ReLU, write once.
// ---------------------------------------------------------------------------
__device__ __forceinline__ void half8_fma(float4& a0, float4& a1,
                                          uint4 raw, float v)
{
    float2 f0 = __half22float2(*reinterpret_cast<__half2*>(&raw.x));
    float2 f1 = __half22float2(*reinterpret_cast<__half2*>(&raw.y));
    float2 f2 = __half22float2(*reinterpret_cast<__half2*>(&raw.z));
    float2 f3 = __half22float2(*reinterpret_cast<__half2*>(&raw.w));
    a0.x = fmaf(v, f0.x, a0.x);  a0.y = fmaf(v, f0.y, a0.y);
    a0.z = fmaf(v, f1.x, a0.z);  a0.w = fmaf(v, f1.y, a0.w);
    a1.x = fmaf(v, f2.x, a1.x);  a1.y = fmaf(v, f2.y, a1.y);
    a1.z = fmaf(v, f3.x, a1.z);  a1.w = fmaf(v, f3.y, a1.w);
}

__global__ __launch_bounds__(256)
void gather_kernel(float* __restrict__ zu, float* __restrict__ zv)
{
    const int side = blockIdx.y;
    const long long t = (long long)blockIdx.x * 256 + threadIdx.x;
    const int seg  = (int)(t >> 3);
    const int lane = (int)(t & 7);
    if (seg >= SEG) return;

    const int s = seg / N_U;            // N_U == N_V
    const int orow = seg - s * N_U;
    const int off = s * CHUNK + lane * 8;

    const int2*   recs = side ? g_ev : g_eu;
    const __half* Y    = side ? g_Yu : g_Yv;
    float*        out  = side ? zv   : zu;
    const int*    ends = side ? g_off_v : g_off_u;

    const int end = __ldg(ends + seg);
    int e = seg ? __ldg(ends + seg - 1) : 0;

    float4 acc0 = make_float4(0.f, 0.f, 0.f, 0.f);
    float4 acc1 = make_float4(0.f, 0.f, 0.f, 0.f);

    // x4 unroll: 4 independent record+row load chains in flight
    for (; e + 4 <= end; e += 4) {
        int2 r0 = __ldg(recs + e);
        int2 r1 = __ldg(recs + e + 1);
        int2 r2 = __ldg(recs + e + 2);
        int2 r3 = __ldg(recs + e + 3);
        uint4 w0 = *reinterpret_cast<const uint4*>(Y + (size_t)r0.x * D_OUT + off);
        uint4 w1 = *reinterpret_cast<const uint4*>(Y + (size_t)r1.x * D_OUT + off);
        uint4 w2 = *reinterpret_cast<const uint4*>(Y + (size_t)r2.x * D_OUT + off);
        uint4 w3 = *reinterpret_cast<const uint4*>(Y + (size_t)r3.x * D_OUT + off);
        half8_fma(acc0, acc1, w0, __int_as_float(r0.y));
        half8_fma(acc0, acc1, w1, __int_as_float(r1.y));
        half8_fma(acc0, acc1, w2, __int_as_float(r2.y));
        half8_fma(acc0, acc1, w3, __int_as_float(r3.y));
    }
    for (; e < end; e++) {
        int2 rec = __ldg(recs + e);
        uint4 raw = *reinterpret_cast<const uint4*>(Y + (size_t)rec.x * D_OUT + off);
        half8_fma(acc0, acc1, raw, __int_as_float(rec.y));
    }
    acc0.x = fmaxf(acc0.x, 0.f);  acc0.y = fmaxf(acc0.y, 0.f);
    acc0.z = fmaxf(acc0.z, 0.f);  acc0.w = fmaxf(acc0.w, 0.f);
    acc1.x = fmaxf(acc1.x, 0.f);  acc1.y = fmaxf(acc1.y, 0.f);
    acc1.z = fmaxf(acc1.z, 0.f);  acc1.w = fmaxf(acc1.w, 0.f);
    float* dst = out + (size_t)orow * D_OUT + off;
    *reinterpret_cast<float4*>(dst)     = acc0;
    *reinterpret_cast<float4*>(dst + 4) = acc1;
}

// ---------------------------------------------------------------------------
// Launch. Side stream properly FORKED from the capture origin stream via an
// event (required for graph capture), then joined back before the gather.
// Submission order puts the GEMM at launch slot 6 (memsets count as
// launches; events do not): memsetU(1) memsetV(2) hist(3) scan1(4) scan2(5)
// GEMM(6) scan3(7) fill(8) gather(9) -> ncu -s 5 -c 1 profiles the GEMM.
// Execution dependencies are identical to the proven 602us version.
// ---------------------------------------------------------------------------
extern "C" void kernel_launch(void* const* d_in, const int* in_sizes, int n_in,
                              void* d_out, int out_size)
{
    const float* x_u      = (const float*)d_in[0];  // [N_U, D_IN]
    const float* x_v      = (const float*)d_in[1];  // [N_V, D_IN]
    const float* W        = (const float*)d_in[2];  // [D_IN, D_OUT]
    const float* sup_vals = (const float*)d_in[3];  // [S, E]
    const int*   sup_rows = (const int*)  d_in[4];  // [S, E]
    const int*   sup_cols = (const int*)  d_in[5];  // [S, E]

    float* zu = (float*)d_out;                       // [N_U, D_OUT]
    float* zv = zu + (size_t)N_U * D_OUT;            // [N_V, D_OUT]

    __half* dYu = nullptr;
    __half* dYv = nullptr;
    void*   dOffU = nullptr;
    void*   dOffV = nullptr;
    cudaGetSymbolAddress((void**)&dYu, g_Yu);
    cudaGetSymbolAddress((void**)&dYv, g_Yv);
    cudaGetSymbolAddress(&dOffU, g_off_u);
    cudaGetSymbolAddress(&dOffV, g_off_v);

    cudaFuncSetAttribute(gemm_tf32_kernel,
                         cudaFuncAttributeMaxDynamicSharedMemorySize,
                         GEMM_SMEM_BYTES);

    cudaStream_t s2;
    cudaEvent_t evFork, evJoin;
    cudaStreamCreateWithFlags(&s2, cudaStreamNonBlocking);
    cudaEventCreateWithFlags(&evFork, cudaEventDisableTiming);
    cudaEventCreateWithFlags(&evJoin, cudaEventDisableTiming);

    // fork side stream from the capture origin stream (REQUIRED for capture)
    cudaEventRecord(evFork, 0);
    cudaStreamWaitEvent(s2, evFork, 0);

    // --- side stream: CSR build, first portion ---
    cudaMemsetAsync(dOffU, 0, SEG * sizeof(int), s2);
    cudaMemsetAsync(dOffV, 0, SEG * sizeof(int), s2);
    {
        int threads = 256;
        int blocks = (TOT_E / 2 + threads - 1) / threads;
        hist_kernel<<<blocks, threads, 0, s2>>>(sup_rows, sup_cols);
        dim3 g1(NBLK, 2);
        scan1_kernel<<<g1, 1024, 0, s2>>>();
        dim3 g2(1, 2);
        scan2_kernel<<<g2, 512, 0, s2>>>();
    }

    // --- main stream: both GEMMs in one launch (6th launch submission) ---
    {
        dim3 grid(D_OUT / GBN, (N_U + GBM - 1) / GBM, 2);   // x = N tile (fast)
        gemm_tf32_kernel<<<grid, 256, GEMM_SMEM_BYTES>>>(x_u, x_v, W, dYu, dYv, N_U);
    }

    // --- side stream: finish CSR build ---
    {
        int threads = 256;
        int blocks = (TOT_E / 2 + threads - 1) / threads;
        dim3 g3(NBLK, 2);
        scan3_kernel<<<g3, 1024, 0, s2>>>();
        fill_kernel<<<blocks, threads, 0, s2>>>(sup_vals, sup_rows, sup_cols);
    }

    // join side stream into the main stream
    cudaEventRecord(evJoin, s2);
    cudaStreamWaitEvent(0, evJoin, 0);

    // --- gather with fused ReLU ---
    {
        long long total = (long long)SEG * 8;
        dim3 grid((unsigned)((total + 255) / 256), 2);
        gather_kernel<<<grid, 256>>>(zu, zv);
    }
}

// round 15
// speedup vs baseline: 2.3240x; 1.0535x over previous
#include <cuda_runtime.h>
#include <cuda_fp16.h>
#include <cstdint>

// Problem constants (match reference)
#define N_U   100000
#define N_V   100000
#define D_IN  256
#define D_OUT 320
#define S_REL 5
#define E_REL 500000
#define CHUNK 64                    // D_OUT / S_REL
#define TOT_E (S_REL * E_REL)       // 2,500,000
#define SEG   (S_REL * N_U)         // 500,000 segments per side
#define NBLK  ((SEG + 1023) / 1024) // 489 scan blocks

// ---------------------------------------------------------------------------
// Scratch (static bss; no allocations). Y stored fp16 (gather accumulates in
// fp32) -> halves random-gather traffic; per-relation Y slice = 12.8 MB,
// L2-resident.
// ---------------------------------------------------------------------------
__device__ __half g_Yu[(size_t)N_U * D_OUT];  // x_u @ W
__device__ __half g_Yv[(size_t)N_V * D_OUT];  // x_v @ W
__device__ int    g_off_u[SEG];               // counts -> exclusive offs -> ends
__device__ int    g_off_v[SEG];
__device__ int2   g_eu[TOT_E];                // records for zu: (col, val-bits)
__device__ int2   g_ev[TOT_E];                // records for zv: (row, val-bits)
__device__ int    g_bsum[2][512];             // scan block sums

// ---------------------------------------------------------------------------
// FP16 tensor-core GEMM (m16n8k16, fp32 accumulate): C = A @ B, C in fp16.
// fp16 and tf32 have identical 11-bit significands -> precision-neutral vs
// the previous tf32 kernel, but k16 per mma HALVES smem fragment traffic
// (the profiled bottleneck: L1 80.4%, tensor 39.6%).
// Double-buffered STATIC smem (29.7 KB), register-staged global prefetch.
// Smem holds half2 (k-pair) words; fragment index math is the tf32 code
// with k -> k2 units. blockIdx.z selects the (A, C) pair.
// ---------------------------------------------------------------------------
#define GBM 128
#define GBN 64
#define GBK 32
#define BK2 (GBK / 2)         // 16 half2 k-pairs
#define KSTEPS (D_IN / GBK)   // 8

#define AS2_STRIDE (BK2 + 4)  // 20: bank (20*gid + tig) % 32 is a permutation
#define BS2_STRIDE (GBN + 8)  // 72: bank (8*tig + 8*ni + gid) % 32 permutation

__device__ __forceinline__ uint32_t f2h2(float a, float b)
{
    __half2 h = __floats2half2_rn(a, b);   // low = a (even k), high = b (odd k)
    return *reinterpret_cast<uint32_t*>(&h);
}

__device__ __forceinline__ void mma_f16(float c[4],
                                        uint32_t a0, uint32_t a1,
                                        uint32_t a2, uint32_t a3,
                                        uint32_t b0, uint32_t b1)
{
    asm volatile(
        "mma.sync.aligned.m16n8k16.row.col.f32.f16.f16.f32 "
        "{%0,%1,%2,%3}, {%4,%5,%6,%7}, {%8,%9}, {%0,%1,%2,%3};"
        : "+f"(c[0]), "+f"(c[1]), "+f"(c[2]), "+f"(c[3])
        : "r"(a0), "r"(a1), "r"(a2), "r"(a3), "r"(b0), "r"(b1));
}

__global__ __launch_bounds__(256)
void gemm_f16_kernel(const float* __restrict__ Au, const float* __restrict__ Av,
                     const float* __restrict__ B,
                     __half* __restrict__ Cu, __half* __restrict__ Cv, int M)
{
    __shared__ uint32_t As2[2][GBM][AS2_STRIDE];   // 2*128*20*4 = 20.5 KB
    __shared__ uint32_t Bs2[2][BK2][BS2_STRIDE];   // 2*16*72*4  =  9.2 KB

    const float* A = blockIdx.z ? Av : Au;
    __half*      C = blockIdx.z ? Cv : Cu;

    const int tid  = threadIdx.x;
    const int lane = tid & 31;
    const int wid  = tid >> 5;
    const int warpM = wid & 3;
    const int warpN = wid >> 2;
    const int gid = lane >> 2;
    const int tig = lane & 3;

    const int blockRow = blockIdx.y * GBM;   // M tile (slow dim)
    const int blockCol = blockIdx.x * GBN;   // N tile (fast dim -> A L2 reuse)

    float acc[2][4][4];
#pragma unroll
    for (int mi = 0; mi < 2; mi++)
#pragma unroll
        for (int ni = 0; ni < 4; ni++)
#pragma unroll
            for (int q = 0; q < 4; q++) acc[mi][ni][q] = 0.f;

    float4 aReg[4];
    float4 bLo, bHi;
    const int kp = tid >> 4;          // 0..15 (k2 row this thread fills in B)
    const int c4 = (tid & 15) * 4;    // 0..60 (col group)

    auto load_tile = [&](int kb) {
#pragma unroll
        for (int it = 0; it < 4; it++) {
            int f   = tid + it * 256;        // 0..1023
            int row = f >> 3;                // 0..127
            int col = (f & 7) * 4;           // f32 col 0..28
            int gr  = blockRow + row;
            aReg[it] = make_float4(0.f, 0.f, 0.f, 0.f);
            if (gr < M)
                aReg[it] = *reinterpret_cast<const float4*>(
                    A + (size_t)gr * D_IN + kb * GBK + col);
        }
        bLo = *reinterpret_cast<const float4*>(
            B + (size_t)(kb * GBK + 2 * kp    ) * D_OUT + blockCol + c4);
        bHi = *reinterpret_cast<const float4*>(
            B + (size_t)(kb * GBK + 2 * kp + 1) * D_OUT + blockCol + c4);
    };

    auto store_tile = [&](int buf) {
#pragma unroll
        for (int it = 0; it < 4; it++) {
            int f   = tid + it * 256;
            int row = f >> 3;
            int k2  = (f & 7) * 2;           // half2-pair index 0..14
            uint2 t;
            t.x = f2h2(aReg[it].x, aReg[it].y);   // k = col, col+1
            t.y = f2h2(aReg[it].z, aReg[it].w);   // k = col+2, col+3
            *reinterpret_cast<uint2*>(&As2[buf][row][k2]) = t;
        }
        uint4 tb;
        tb.x = f2h2(bLo.x, bHi.x);   // (k even, k odd) for col c4
        tb.y = f2h2(bLo.y, bHi.y);
        tb.z = f2h2(bLo.z, bHi.z);
        tb.w = f2h2(bLo.w, bHi.w);
        *reinterpret_cast<uint4*>(&Bs2[buf][kp][c4]) = tb;
    };

    auto compute_tile = [&](int buf) {
#pragma unroll
        for (int ks = 0; ks < 2; ks++) {     // two k16 steps per BK=32 tile
            const int kk2 = ks * 8;          // k2 offset
            uint32_t af[2][4];
#pragma unroll
            for (int mi = 0; mi < 2; mi++) {
                int rb = warpM * 32 + mi * 16 + gid;
                af[mi][0] = As2[buf][rb    ][kk2 + tig    ];
                af[mi][1] = As2[buf][rb + 8][kk2 + tig    ];
                af[mi][2] = As2[buf][rb    ][kk2 + tig + 4];
                af[mi][3] = As2[buf][rb + 8][kk2 + tig + 4];
            }
            uint32_t bf[4][2];
#pragma unroll
            for (int ni = 0; ni < 4; ni++) {
                int cb = warpN * 32 + ni * 8 + gid;
                bf[ni][0] = Bs2[buf][kk2 + tig    ][cb];
                bf[ni][1] = Bs2[buf][kk2 + tig + 4][cb];
            }
#pragma unroll
            for (int mi = 0; mi < 2; mi++)
#pragma unroll
                for (int ni = 0; ni < 4; ni++)
                    mma_f16(acc[mi][ni],
                            af[mi][0], af[mi][1], af[mi][2], af[mi][3],
                            bf[ni][0], bf[ni][1]);
        }
    };

    load_tile(0);
    store_tile(0);
    __syncthreads();

#pragma unroll
    for (int kb = 0; kb < KSTEPS; kb++) {
        if (kb + 1 < KSTEPS)
            load_tile(kb + 1);
        compute_tile(kb & 1);
        if (kb + 1 < KSTEPS) {
            store_tile((kb + 1) & 1);
            __syncthreads();
        }
    }

    // ---- epilogue: fp32 accum -> fp16 stores (2 cols per 4B) ----
#pragma unroll
    for (int mi = 0; mi < 2; mi++) {
        int r0 = blockRow + warpM * 32 + mi * 16 + gid;
#pragma unroll
        for (int ni = 0; ni < 4; ni++) {
            int cc = blockCol + warpN * 32 + ni * 8 + tig * 2;
            if (r0 < M) {
                __half2 h = __floats2half2_rn(acc[mi][ni][0], acc[mi][ni][1]);
                *reinterpret_cast<__half2*>(C + (size_t)r0 * D_OUT + cc) = h;
            }
            if (r0 + 8 < M) {
                __half2 h = __floats2half2_rn(acc[mi][ni][2], acc[mi][ni][3]);
                *reinterpret_cast<__half2*>(C + (size_t)(r0 + 8) * D_OUT + cc) = h;
            }
        }
    }
}

// ---------------------------------------------------------------------------
// CSR build step 1: histogram; 2 edges per thread (E_REL even -> a pair never
// straddles a relation boundary; 8B-aligned vector loads).
// ---------------------------------------------------------------------------
__global__ __launch_bounds__(256)
void hist_kernel(const int* __restrict__ rows, const int* __restrict__ cols)
{
    int e = (blockIdx.x * blockDim.x + threadIdx.x) * 2;
    if (e >= TOT_E) return;
    int s = e / E_REL;
    int2 r2 = *reinterpret_cast<const int2*>(rows + e);
    int2 c2 = *reinterpret_cast<const int2*>(cols + e);
    atomicAdd(&g_off_u[s * N_U + r2.x], 1);
    atomicAdd(&g_off_u[s * N_U + r2.y], 1);
    atomicAdd(&g_off_v[s * N_V + c2.x], 1);
    atomicAdd(&g_off_v[s * N_V + c2.y], 1);
}

// ---------------------------------------------------------------------------
// CSR build step 2: two-level exclusive scan over 500k counters (both sides)
// ---------------------------------------------------------------------------
__global__ __launch_bounds__(1024)
void scan1_kernel()
{
    __shared__ int sh[1024];
    int* buf = blockIdx.y ? g_off_v : g_off_u;
    int tid = threadIdx.x;
    int gid = blockIdx.x * 1024 + tid;
    int v = (gid < SEG) ? buf[gid] : 0;
    sh[tid] = v;
    __syncthreads();
#pragma unroll
    for (int d = 1; d < 1024; d <<= 1) {
        int t = (tid >= d) ? sh[tid - d] : 0;
        __syncthreads();
        sh[tid] += t;
        __syncthreads();
    }
    if (gid < SEG) buf[gid] = sh[tid] - v;     // exclusive
    if (tid == 1023) g_bsum[blockIdx.y][blockIdx.x] = sh[1023];
}

__global__ __launch_bounds__(512)
void scan2_kernel()
{
    __shared__ int sh[512];
    int tid = threadIdx.x;
    int side = blockIdx.y;
    int v = (tid < NBLK) ? g_bsum[side][tid] : 0;
    sh[tid] = v;
    __syncthreads();
#pragma unroll
    for (int d = 1; d < 512; d <<= 1) {
        int t = (tid >= d) ? sh[tid - d] : 0;
        __syncthreads();
        sh[tid] += t;
        __syncthreads();
    }
    if (tid < NBLK) g_bsum[side][tid] = sh[tid] - v;  // exclusive
}

__global__ __launch_bounds__(1024)
void scan3_kernel()
{
    int* buf = blockIdx.y ? g_off_v : g_off_u;
    int gid = blockIdx.x * 1024 + threadIdx.x;
    if (gid < SEG) buf[gid] += g_bsum[blockIdx.y][blockIdx.x];
}

// ---------------------------------------------------------------------------
// CSR build step 3: fill records; 2 edges per thread.
// Afterwards g_off_*[seg] holds the END of segment seg.
// ---------------------------------------------------------------------------
__global__ __launch_bounds__(256)
void fill_kernel(const float* __restrict__ vals,
                 const int*   __restrict__ rows,
                 const int*   __restrict__ cols)
{
    int e = (blockIdx.x * blockDim.x + threadIdx.x) * 2;
    if (e >= TOT_E) return;
    int s = e / E_REL;
    int2   r2 = *reinterpret_cast<const int2*>(rows + e);
    int2   c2 = *reinterpret_cast<const int2*>(cols + e);
    float2 v2 = *reinterpret_cast<const float2*>(vals + e);

    int pu0 = atomicAdd(&g_off_u[s * N_U + r2.x], 1);
    g_eu[pu0] = make_int2(c2.x, __float_as_int(v2.x));
    int pu1 = atomicAdd(&g_off_u[s * N_U + r2.y], 1);
    g_eu[pu1] = make_int2(c2.y, __float_as_int(v2.y));

    int pv0 = atomicAdd(&g_off_v[s * N_V + c2.x], 1);
    g_ev[pv0] = make_int2(r2.x, __float_as_int(v2.x));
    int pv1 = atomicAdd(&g_off_v[s * N_V + c2.y], 1);
    g_ev[pv1] = make_int2(r2.y, __float_as_int(v2.y));
}

// ---------------------------------------------------------------------------
// Gather: 8 threads per (s, out_row) segment, each owns 8 cols of the
// 64-wide chunk (one 16B load per edge per lane; the 8 lanes of a segment
// cover a coalesced 128B row read per edge). fp32 accumulate, unrolled x4
// for MLP, fused ReLU, write once.
// ---------------------------------------------------------------------------
__device__ __forceinline__ void half8_fma(float4& a0, float4& a1,
                                          uint4 raw, float v)
{
    float2 f0 = __half22float2(*reinterpret_cast<__half2*>(&raw.x));
    float2 f1 = __half22float2(*reinterpret_cast<__half2*>(&raw.y));
    float2 f2 = __half22float2(*reinterpret_cast<__half2*>(&raw.z));
    float2 f3 = __half22float2(*reinterpret_cast<__half2*>(&raw.w));
    a0.x = fmaf(v, f0.x, a0.x);  a0.y = fmaf(v, f0.y, a0.y);
    a0.z = fmaf(v, f1.x, a0.z);  a0.w = fmaf(v, f1.y, a0.w);
    a1.x = fmaf(v, f2.x, a1.x);  a1.y = fmaf(v, f2.y, a1.y);
    a1.z = fmaf(v, f3.x, a1.z);  a1.w = fmaf(v, f3.y, a1.w);
}

__global__ __launch_bounds__(256)
void gather_kernel(float* __restrict__ zu, float* __restrict__ zv)
{
    const int side = blockIdx.y;
    const long long t = (long long)blockIdx.x * 256 + threadIdx.x;
    const int seg  = (int)(t >> 3);
    const int lane = (int)(t & 7);
    if (seg >= SEG) return;

    const int s = seg / N_U;            // N_U == N_V
    const int orow = seg - s * N_U;
    const int off = s * CHUNK + lane * 8;

    const int2*   recs = side ? g_ev : g_eu;
    const __half* Y    = side ? g_Yu : g_Yv;
    float*        out  = side ? zv   : zu;
    const int*    ends = side ? g_off_v : g_off_u;

    const int end = __ldg(ends + seg);
    int e = seg ? __ldg(ends + seg - 1) : 0;

    float4 acc0 = make_float4(0.f, 0.f, 0.f, 0.f);
    float4 acc1 = make_float4(0.f, 0.f, 0.f, 0.f);

    // x4 unroll: 4 independent record+row load chains in flight
    for (; e + 4 <= end; e += 4) {
        int2 r0 = __ldg(recs + e);
        int2 r1 = __ldg(recs + e + 1);
        int2 r2 = __ldg(recs + e + 2);
        int2 r3 = __ldg(recs + e + 3);
        uint4 w0 = *reinterpret_cast<const uint4*>(Y + (size_t)r0.x * D_OUT + off);
        uint4 w1 = *reinterpret_cast<const uint4*>(Y + (size_t)r1.x * D_OUT + off);
        uint4 w2 = *reinterpret_cast<const uint4*>(Y + (size_t)r2.x * D_OUT + off);
        uint4 w3 = *reinterpret_cast<const uint4*>(Y + (size_t)r3.x * D_OUT + off);
        half8_fma(acc0, acc1, w0, __int_as_float(r0.y));
        half8_fma(acc0, acc1, w1, __int_as_float(r1.y));
        half8_fma(acc0, acc1, w2, __int_as_float(r2.y));
        half8_fma(acc0, acc1, w3, __int_as_float(r3.y));
    }
    for (; e < end; e++) {
        int2 rec = __ldg(recs + e);
        uint4 raw = *reinterpret_cast<const uint4*>(Y + (size_t)rec.x * D_OUT + off);
        half8_fma(acc0, acc1, raw, __int_as_float(rec.y));
    }
    acc0.x = fmaxf(acc0.x, 0.f);  acc0.y = fmaxf(acc0.y, 0.f);
    acc0.z = fmaxf(acc0.z, 0.f);  acc0.w = fmaxf(acc0.w, 0.f);
    acc1.x = fmaxf(acc1.x, 0.f);  acc1.y = fmaxf(acc1.y, 0.f);
    acc1.z = fmaxf(acc1.z, 0.f);  acc1.w = fmaxf(acc1.w, 0.f);
    float* dst = out + (size_t)orow * D_OUT + off;
    *reinterpret_cast<float4*>(dst)     = acc0;
    *reinterpret_cast<float4*>(dst + 4) = acc1;
}

// ---------------------------------------------------------------------------
// Launch. Side stream FORKED from the capture origin via an event (required
// for graph capture), joined back before the gather. Submission order keeps
// the GEMM at launch slot 6 so ncu -s 5 -c 1 profiles it:
//   memsetU(1) memsetV(2) hist(3) scan1(4) scan2(5) GEMM(6) scan3(7)
//   fill(8) gather(9)
// ---------------------------------------------------------------------------
extern "C" void kernel_launch(void* const* d_in, const int* in_sizes, int n_in,
                              void* d_out, int out_size)
{
    const float* x_u      = (const float*)d_in[0];  // [N_U, D_IN]
    const float* x_v      = (const float*)d_in[1];  // [N_V, D_IN]
    const float* W        = (const float*)d_in[2];  // [D_IN, D_OUT]
    const float* sup_vals = (const float*)d_in[3];  // [S, E]
    const int*   sup_rows = (const int*)  d_in[4];  // [S, E]
    const int*   sup_cols = (const int*)  d_in[5];  // [S, E]

    float* zu = (float*)d_out;                       // [N_U, D_OUT]
    float* zv = zu + (size_t)N_U * D_OUT;            // [N_V, D_OUT]

    __half* dYu = nullptr;
    __half* dYv = nullptr;
    void*   dOffU = nullptr;
    void*   dOffV = nullptr;
    cudaGetSymbolAddress((void**)&dYu, g_Yu);
    cudaGetSymbolAddress((void**)&dYv, g_Yv);
    cudaGetSymbolAddress(&dOffU, g_off_u);
    cudaGetSymbolAddress(&dOffV, g_off_v);

    cudaStream_t s2;
    cudaEvent_t evFork, evJoin;
    cudaStreamCreateWithFlags(&s2, cudaStreamNonBlocking);
    cudaEventCreateWithFlags(&evFork, cudaEventDisableTiming);
    cudaEventCreateWithFlags(&evJoin, cudaEventDisableTiming);

    // fork side stream from the capture origin stream (REQUIRED for capture)
    cudaEventRecord(evFork, 0);
    cudaStreamWaitEvent(s2, evFork, 0);

    // --- side stream: CSR build, first portion ---
    cudaMemsetAsync(dOffU, 0, SEG * sizeof(int), s2);
    cudaMemsetAsync(dOffV, 0, SEG * sizeof(int), s2);
    {
        int threads = 256;
        int blocks = (TOT_E / 2 + threads - 1) / threads;
        hist_kernel<<<blocks, threads, 0, s2>>>(sup_rows, sup_cols);
        dim3 g1(NBLK, 2);
        scan1_kernel<<<g1, 1024, 0, s2>>>();
        dim3 g2(1, 2);
        scan2_kernel<<<g2, 512, 0, s2>>>();
    }

    // --- main stream: both GEMMs in one launch (6th launch submission) ---
    {
        dim3 grid(D_OUT / GBN, (N_U + GBM - 1) / GBM, 2);   // x = N tile (fast)
        gemm_f16_kernel<<<grid, 256>>>(x_u, x_v, W, dYu, dYv, N_U);
    }

    // --- side stream: finish CSR build ---
    {
        int threads = 256;
        int blocks = (TOT_E / 2 + threads - 1) / threads;
        dim3 g3(NBLK, 2);
        scan3_kernel<<<g3, 1024, 0, s2>>>();
        fill_kernel<<<blocks, threads, 0, s2>>>(sup_vals, sup_rows, sup_cols);
    }

    // join side stream into the main stream
    cudaEventRecord(evJoin, s2);
    cudaStreamWaitEvent(0, evJoin, 0);

    // --- gather with fused ReLU ---
    {
        long long total = (long long)SEG * 8;
        dim3 grid((unsigned)((total + 255) / 256), 2);
        gather_kernel<<<grid, 256>>>(zu, zv);
    }
}

// round 16
// speedup vs baseline: 2.5058x; 1.0782x over previous
#include <cuda_runtime.h>
#include <cuda_fp16.h>
#include <cstdint>

// Problem constants (match reference)
#define N_U   100000
#define N_V   100000
#define D_IN  256
#define D_OUT 320
#define S_REL 5
#define E_REL 500000
#define CHUNK 64                    // D_OUT / S_REL
#define TOT_E (S_REL * E_REL)       // 2,500,000
#define SEG   (S_REL * N_U)         // 500,000 segments per side
#define NBLK  ((SEG + 1023) / 1024) // 489 scan blocks

// ---------------------------------------------------------------------------
// Scratch (static bss; no allocations).
// ---------------------------------------------------------------------------
__device__ __half    g_Yu[(size_t)N_U * D_OUT];   // x_u @ W (fp16)
__device__ __half    g_Yv[(size_t)N_V * D_OUT];
__device__ __half    g_Xuh[(size_t)N_U * D_IN];   // x_u in fp16 (row major)
__device__ __half    g_Xvh[(size_t)N_V * D_IN];
__device__ uint32_t  g_W2[(D_IN / 2) * D_OUT];    // W k-pair interleaved:
                                                  // W2[kp*320+n]=(W[2kp][n],W[2kp+1][n])
__device__ int    g_off_u[SEG];
__device__ int    g_off_v[SEG];
__device__ int2   g_eu[TOT_E];
__device__ int2   g_ev[TOT_E];
__device__ int    g_bsum[2][512];

__device__ __forceinline__ uint32_t f2h2(float a, float b)
{
    __half2 h = __floats2half2_rn(a, b);
    return *reinterpret_cast<uint32_t*>(&h);
}

// ---------------------------------------------------------------------------
// Input conversion: z=0 -> Xu fp16, z=1 -> Xv fp16, z=2 -> W interleaved.
// ---------------------------------------------------------------------------
__global__ __launch_bounds__(256)
void convert_kernel(const float* __restrict__ xu, const float* __restrict__ xv,
                    const float* __restrict__ W)
{
    if (blockIdx.z < 2) {
        const float4* src = reinterpret_cast<const float4*>(blockIdx.z ? xv : xu);
        uint2* dst = reinterpret_cast<uint2*>(blockIdx.z ? g_Xvh : g_Xuh);
        const int n4 = N_U * D_IN / 4;
        for (int i = blockIdx.x * 256 + threadIdx.x; i < n4; i += gridDim.x * 256) {
            float4 v = src[i];
            uint2 h;
            h.x = f2h2(v.x, v.y);
            h.y = f2h2(v.z, v.w);
            dst[i] = h;
        }
    } else {
        const int total = (D_IN / 2) * D_OUT;
        for (int i = blockIdx.x * 256 + threadIdx.x; i < total; i += gridDim.x * 256) {
            int kp = i / D_OUT;
            int n  = i - kp * D_OUT;
            g_W2[i] = f2h2(W[(2 * kp) * D_OUT + n], W[(2 * kp + 1) * D_OUT + n]);
        }
    }
}

// ---------------------------------------------------------------------------
// FP16 tensor-core GEMM (m16n8k16, fp32 accumulate), cp.async pipeline.
// No register staging -> ~60 regs -> 4 CTAs/SM (occ 48%, was 24%).
// Fragment indexing and smem strides identical to the verified R14 kernel.
// ---------------------------------------------------------------------------
#define GBM 128
#define GBN 64
#define GBK 32
#define BK2 (GBK / 2)         // 16 half2 k-pairs
#define KSTEPS (D_IN / GBK)   // 8

#define AS2_STRIDE 20         // uint32 words/row (16 data + 4 pad); 80B, 16B-aligned
#define BS2_STRIDE 72         // uint32 words/row (64 data + 8 pad); 288B, 16B-aligned

__device__ __forceinline__ void cp_async16(uint32_t smem_addr, const void* gptr,
                                           int src_bytes)
{
    asm volatile("cp.async.ca.shared.global [%0], [%1], 16, %2;"
                 :: "r"(smem_addr), "l"(gptr), "r"(src_bytes));
}
#define CP_COMMIT()  asm volatile("cp.async.commit_group;")
#define CP_WAIT(n)   asm volatile("cp.async.wait_group %0;" :: "n"(n))

__device__ __forceinline__ void mma_f16(float c[4],
                                        uint32_t a0, uint32_t a1,
                                        uint32_t a2, uint32_t a3,
                                        uint32_t b0, uint32_t b1)
{
    asm volatile(
        "mma.sync.aligned.m16n8k16.row.col.f32.f16.f16.f32 "
        "{%0,%1,%2,%3}, {%4,%5,%6,%7}, {%8,%9}, {%0,%1,%2,%3};"
        : "+f"(c[0]), "+f"(c[1]), "+f"(c[2]), "+f"(c[3])
        : "r"(a0), "r"(a1), "r"(a2), "r"(a3), "r"(b0), "r"(b1));
}

__global__ __launch_bounds__(256, 4)
void gemm_f16_kernel(__half* __restrict__ Cu, __half* __restrict__ Cv, int M)
{
    __shared__ uint32_t As2[2][GBM][AS2_STRIDE];   // 20.5 KB
    __shared__ uint32_t Bs2[2][BK2][BS2_STRIDE];   //  9.2 KB

    const __half* A = blockIdx.z ? g_Xvh : g_Xuh;
    __half*       C = blockIdx.z ? Cv : Cu;

    const int tid  = threadIdx.x;
    const int lane = tid & 31;
    const int wid  = tid >> 5;
    const int warpM = wid & 3;
    const int warpN = wid >> 2;
    const int gid = lane >> 2;
    const int tig = lane & 3;

    const int blockRow = blockIdx.y * GBM;   // M tile (slow dim)
    const int blockCol = blockIdx.x * GBN;   // N tile (fast dim)

    float acc[2][4][4];
#pragma unroll
    for (int mi = 0; mi < 2; mi++)
#pragma unroll
        for (int ni = 0; ni < 4; ni++)
#pragma unroll
            for (int q = 0; q < 4; q++) acc[mi][ni][q] = 0.f;

    // Per-thread cp.async coordinates (fixed across K-tiles)
    const int arow0 = tid >> 2;          // A: rows 0..63  (it=0)
    const int ach   = (tid & 3);         // A: 16B chunk 0..3 within 64B row
    const int bkp   = tid >> 4;          // B: kp row 0..15
    const int bch   = tid & 15;          // B: 16B chunk 0..15 within 256B row

    auto issue_tile = [&](int kb, int buf) {
        // A tile: 128 rows x 64B = 512 chunks, 2 per thread
#pragma unroll
        for (int it = 0; it < 2; it++) {
            int row = arow0 + it * 64;
            int gr  = blockRow + row;
            const __half* src = A + (size_t)gr * D_IN + kb * GBK + ach * 8;
            uint32_t dst = (uint32_t)__cvta_generic_to_shared(
                &As2[buf][row][ach * 4]);
            cp_async16(dst, src, gr < M ? 16 : 0);
        }
        // B tile: 16 kp-rows x 256B = 256 chunks, 1 per thread
        {
            const uint32_t* src = g_W2 + (size_t)(kb * BK2 + bkp) * D_OUT
                                  + blockCol + bch * 4;
            uint32_t dst = (uint32_t)__cvta_generic_to_shared(
                &Bs2[buf][bkp][bch * 4]);
            cp_async16(dst, src, 16);
        }
    };

    auto compute_tile = [&](int buf) {
#pragma unroll
        for (int ks = 0; ks < 2; ks++) {
            const int kk2 = ks * 8;
            uint32_t af[2][4];
#pragma unroll
            for (int mi = 0; mi < 2; mi++) {
                int rb = warpM * 32 + mi * 16 + gid;
                af[mi][0] = As2[buf][rb    ][kk2 + tig    ];
                af[mi][1] = As2[buf][rb + 8][kk2 + tig    ];
                af[mi][2] = As2[buf][rb    ][kk2 + tig + 4];
                af[mi][3] = As2[buf][rb + 8][kk2 + tig + 4];
            }
            uint32_t bf[4][2];
#pragma unroll
            for (int ni = 0; ni < 4; ni++) {
                int cb = warpN * 32 + ni * 8 + gid;
                bf[ni][0] = Bs2[buf][kk2 + tig    ][cb];
                bf[ni][1] = Bs2[buf][kk2 + tig + 4][cb];
            }
#pragma unroll
            for (int mi = 0; mi < 2; mi++)
#pragma unroll
                for (int ni = 0; ni < 4; ni++)
                    mma_f16(acc[mi][ni],
                            af[mi][0], af[mi][1], af[mi][2], af[mi][3],
                            bf[ni][0], bf[ni][1]);
        }
    };

    issue_tile(0, 0);
    CP_COMMIT();

#pragma unroll
    for (int kb = 0; kb < KSTEPS; kb++) {
        if (kb + 1 < KSTEPS) {
            issue_tile(kb + 1, (kb + 1) & 1);
            CP_COMMIT();
            CP_WAIT(1);               // tile kb done; kb+1 may be in flight
        } else {
            CP_WAIT(0);
        }
        __syncthreads();              // copies visible to all warps
        compute_tile(kb & 1);
        if (kb + 1 < KSTEPS)
            __syncthreads();          // release buf before it is re-issued
    }

    // ---- epilogue: fp32 accum -> fp16 stores (2 cols per 4B) ----
#pragma unroll
    for (int mi = 0; mi < 2; mi++) {
        int r0 = blockRow + warpM * 32 + mi * 16 + gid;
#pragma unroll
        for (int ni = 0; ni < 4; ni++) {
            int cc = blockCol + warpN * 32 + ni * 8 + tig * 2;
            if (r0 < M) {
                __half2 h = __floats2half2_rn(acc[mi][ni][0], acc[mi][ni][1]);
                *reinterpret_cast<__half2*>(C + (size_t)r0 * D_OUT + cc) = h;
            }
            if (r0 + 8 < M) {
                __half2 h = __floats2half2_rn(acc[mi][ni][2], acc[mi][ni][3]);
                *reinterpret_cast<__half2*>(C + (size_t)(r0 + 8) * D_OUT + cc) = h;
            }
        }
    }
}

// ---------------------------------------------------------------------------
// CSR build step 1: histogram; 2 edges per thread.
// ---------------------------------------------------------------------------
__global__ __launch_bounds__(256)
void hist_kernel(const int* __restrict__ rows, const int* __restrict__ cols)
{
    int e = (blockIdx.x * blockDim.x + threadIdx.x) * 2;
    if (e >= TOT_E) return;
    int s = e / E_REL;
    int2 r2 = *reinterpret_cast<const int2*>(rows + e);
    int2 c2 = *reinterpret_cast<const int2*>(cols + e);
    atomicAdd(&g_off_u[s * N_U + r2.x], 1);
    atomicAdd(&g_off_u[s * N_U + r2.y], 1);
    atomicAdd(&g_off_v[s * N_V + c2.x], 1);
    atomicAdd(&g_off_v[s * N_V + c2.y], 1);
}

// ---------------------------------------------------------------------------
// CSR build step 2: two-level exclusive scan (both sides)
// ---------------------------------------------------------------------------
__global__ __launch_bounds__(1024)
void scan1_kernel()
{
    __shared__ int sh[1024];
    int* buf = blockIdx.y ? g_off_v : g_off_u;
    int tid = threadIdx.x;
    int gid = blockIdx.x * 1024 + tid;
    int v = (gid < SEG) ? buf[gid] : 0;
    sh[tid] = v;
    __syncthreads();
#pragma unroll
    for (int d = 1; d < 1024; d <<= 1) {
        int t = (tid >= d) ? sh[tid - d] : 0;
        __syncthreads();
        sh[tid] += t;
        __syncthreads();
    }
    if (gid < SEG) buf[gid] = sh[tid] - v;
    if (tid == 1023) g_bsum[blockIdx.y][blockIdx.x] = sh[1023];
}

__global__ __launch_bounds__(512)
void scan2_kernel()
{
    __shared__ int sh[512];
    int tid = threadIdx.x;
    int side = blockIdx.y;
    int v = (tid < NBLK) ? g_bsum[side][tid] : 0;
    sh[tid] = v;
    __syncthreads();
#pragma unroll
    for (int d = 1; d < 512; d <<= 1) {
        int t = (tid >= d) ? sh[tid - d] : 0;
        __syncthreads();
        sh[tid] += t;
        __syncthreads();
    }
    if (tid < NBLK) g_bsum[side][tid] = sh[tid] - v;
}

__global__ __launch_bounds__(1024)
void scan3_kernel()
{
    int* buf = blockIdx.y ? g_off_v : g_off_u;
    int gid = blockIdx.x * 1024 + threadIdx.x;
    if (gid < SEG) buf[gid] += g_bsum[blockIdx.y][blockIdx.x];
}

// ---------------------------------------------------------------------------
// CSR build step 3: fill records; 2 edges per thread.
// ---------------------------------------------------------------------------
__global__ __launch_bounds__(256)
void fill_kernel(const float* __restrict__ vals,
                 const int*   __restrict__ rows,
                 const int*   __restrict__ cols)
{
    int e = (blockIdx.x * blockDim.x + threadIdx.x) * 2;
    if (e >= TOT_E) return;
    int s = e / E_REL;
    int2   r2 = *reinterpret_cast<const int2*>(rows + e);
    int2   c2 = *reinterpret_cast<const int2*>(cols + e);
    float2 v2 = *reinterpret_cast<const float2*>(vals + e);

    int pu0 = atomicAdd(&g_off_u[s * N_U + r2.x], 1);
    g_eu[pu0] = make_int2(c2.x, __float_as_int(v2.x));
    int pu1 = atomicAdd(&g_off_u[s * N_U + r2.y], 1);
    g_eu[pu1] = make_int2(c2.y, __float_as_int(v2.y));

    int pv0 = atomicAdd(&g_off_v[s * N_V + c2.x], 1);
    g_ev[pv0] = make_int2(r2.x, __float_as_int(v2.x));
    int pv1 = atomicAdd(&g_off_v[s * N_V + c2.y], 1);
    g_ev[pv1] = make_int2(r2.y, __float_as_int(v2.y));
}

// ---------------------------------------------------------------------------
// Gather: 8 threads per (s, out_row) segment, 16B fp16 loads, x4 unroll,
// fp32 accumulate, fused ReLU.
// ---------------------------------------------------------------------------
__device__ __forceinline__ void half8_fma(float4& a0, float4& a1,
                                          uint4 raw, float v)
{
    float2 f0 = __half22float2(*reinterpret_cast<__half2*>(&raw.x));
    float2 f1 = __half22float2(*reinterpret_cast<__half2*>(&raw.y));
    float2 f2 = __half22float2(*reinterpret_cast<__half2*>(&raw.z));
    float2 f3 = __half22float2(*reinterpret_cast<__half2*>(&raw.w));
    a0.x = fmaf(v, f0.x, a0.x);  a0.y = fmaf(v, f0.y, a0.y);
    a0.z = fmaf(v, f1.x, a0.z);  a0.w = fmaf(v, f1.y, a0.w);
    a1.x = fmaf(v, f2.x, a1.x);  a1.y = fmaf(v, f2.y, a1.y);
    a1.z = fmaf(v, f3.x, a1.z);  a1.w = fmaf(v, f3.y, a1.w);
}

__global__ __launch_bounds__(256)
void gather_kernel(float* __restrict__ zu, float* __restrict__ zv)
{
    const int side = blockIdx.y;
    const long long t = (long long)blockIdx.x * 256 + threadIdx.x;
    const int seg  = (int)(t >> 3);
    const int lane = (int)(t & 7);
    if (seg >= SEG) return;

    const int s = seg / N_U;
    const int orow = seg - s * N_U;
    const int off = s * CHUNK + lane * 8;

    const int2*   recs = side ? g_ev : g_eu;
    const __half* Y    = side ? g_Yu : g_Yv;
    float*        out  = side ? zv   : zu;
    const int*    ends = side ? g_off_v : g_off_u;

    const int end = __ldg(ends + seg);
    int e = seg ? __ldg(ends + seg - 1) : 0;

    float4 acc0 = make_float4(0.f, 0.f, 0.f, 0.f);
    float4 acc1 = make_float4(0.f, 0.f, 0.f, 0.f);

    for (; e + 4 <= end; e += 4) {
        int2 r0 = __ldg(recs + e);
        int2 r1 = __ldg(recs + e + 1);
        int2 r2 = __ldg(recs + e + 2);
        int2 r3 = __ldg(recs + e + 3);
        uint4 w0 = *reinterpret_cast<const uint4*>(Y + (size_t)r0.x * D_OUT + off);
        uint4 w1 = *reinterpret_cast<const uint4*>(Y + (size_t)r1.x * D_OUT + off);
        uint4 w2 = *reinterpret_cast<const uint4*>(Y + (size_t)r2.x * D_OUT + off);
        uint4 w3 = *reinterpret_cast<const uint4*>(Y + (size_t)r3.x * D_OUT + off);
        half8_fma(acc0, acc1, w0, __int_as_float(r0.y));
        half8_fma(acc0, acc1, w1, __int_as_float(r1.y));
        half8_fma(acc0, acc1, w2, __int_as_float(r2.y));
        half8_fma(acc0, acc1, w3, __int_as_float(r3.y));
    }
    for (; e < end; e++) {
        int2 rec = __ldg(recs + e);
        uint4 raw = *reinterpret_cast<const uint4*>(Y + (size_t)rec.x * D_OUT + off);
        half8_fma(acc0, acc1, raw, __int_as_float(rec.y));
    }
    acc0.x = fmaxf(acc0.x, 0.f);  acc0.y = fmaxf(acc0.y, 0.f);
    acc0.z = fmaxf(acc0.z, 0.f);  acc0.w = fmaxf(acc0.w, 0.f);
    acc1.x = fmaxf(acc1.x, 0.f);  acc1.y = fmaxf(acc1.y, 0.f);
    acc1.z = fmaxf(acc1.z, 0.f);  acc1.w = fmaxf(acc1.w, 0.f);
    float* dst = out + (size_t)orow * D_OUT + off;
    *reinterpret_cast<float4*>(dst)     = acc0;
    *reinterpret_cast<float4*>(dst + 4) = acc1;
}

// ---------------------------------------------------------------------------
// Launch. Side stream forked/joined via events (graph-capture legal).
// Submission order keeps the GEMM at launch slot 6 for ncu -s 5 -c 1:
//   memsetU(1) memsetV(2) hist(3) scan1(4) convert(5) GEMM(6) scan2(7)
//   scan3(8) fill(9) gather(10)
// Stream-order deps: convert -> GEMM on stream 0; CSR chain on s2; gather
// waits on both.
// ---------------------------------------------------------------------------
extern "C" void kernel_launch(void* const* d_in, const int* in_sizes, int n_in,
                              void* d_out, int out_size)
{
    const float* x_u      = (const float*)d_in[0];  // [N_U, D_IN]
    const float* x_v      = (const float*)d_in[1];  // [N_V, D_IN]
    const float* W        = (const float*)d_in[2];  // [D_IN, D_OUT]
    const float* sup_vals = (const float*)d_in[3];  // [S, E]
    const int*   sup_rows = (const int*)  d_in[4];  // [S, E]
    const int*   sup_cols = (const int*)  d_in[5];  // [S, E]

    float* zu = (float*)d_out;                       // [N_U, D_OUT]
    float* zv = zu + (size_t)N_U * D_OUT;            // [N_V, D_OUT]

    __half* dYu = nullptr;
    __half* dYv = nullptr;
    void*   dOffU = nullptr;
    void*   dOffV = nullptr;
    cudaGetSymbolAddress((void**)&dYu, g_Yu);
    cudaGetSymbolAddress((void**)&dYv, g_Yv);
    cudaGetSymbolAddress(&dOffU, g_off_u);
    cudaGetSymbolAddress(&dOffV, g_off_v);

    cudaStream_t s2;
    cudaEvent_t evFork, evJoin;
    cudaStreamCreateWithFlags(&s2, cudaStreamNonBlocking);
    cudaEventCreateWithFlags(&evFork, cudaEventDisableTiming);
    cudaEventCreateWithFlags(&evJoin, cudaEventDisableTiming);

    // fork side stream from the capture origin stream (REQUIRED for capture)
    cudaEventRecord(evFork, 0);
    cudaStreamWaitEvent(s2, evFork, 0);

    // --- side stream: CSR build, first portion ---
    cudaMemsetAsync(dOffU, 0, SEG * sizeof(int), s2);
    cudaMemsetAsync(dOffV, 0, SEG * sizeof(int), s2);
    {
        int threads = 256;
        int blocks = (TOT_E / 2 + threads - 1) / threads;
        hist_kernel<<<blocks, threads, 0, s2>>>(sup_rows, sup_cols);
        dim3 g1(NBLK, 2);
        scan1_kernel<<<g1, 1024, 0, s2>>>();
    }

    // --- main stream: input conversion (5th launch), then GEMM (6th) ---
    {
        dim3 cg(2048, 1, 3);
        convert_kernel<<<cg, 256>>>(x_u, x_v, W);
    }
    {
        dim3 grid(D_OUT / GBN, (N_U + GBM - 1) / GBM, 2);   // x = N tile (fast)
        gemm_f16_kernel<<<grid, 256>>>(dYu, dYv, N_U);
    }

    // --- side stream: finish CSR build ---
    {
        int threads = 256;
        int blocks = (TOT_E / 2 + threads - 1) / threads;
        dim3 g2(1, 2);
        scan2_kernel<<<g2, 512, 0, s2>>>();
        dim3 g3(NBLK, 2);
        scan3_kernel<<<g3, 1024, 0, s2>>>();
        fill_kernel<<<blocks, threads, 0, s2>>>(sup_vals, sup_rows, sup_cols);
    }

    // join side stream into the main stream
    cudaEventRecord(evJoin, s2);
    cudaStreamWaitEvent(0, evJoin, 0);

    // --- gather with fused ReLU ---
    {
        long long total = (long long)SEG * 8;
        dim3 grid((unsigned)((total + 255) / 256), 2);
        gather_kernel<<<grid, 256>>>(zu, zv);
    }
}